// round 1
// baseline (speedup 1.0000x reference)
#include <cuda_runtime.h>
#include <math.h>

#define EMBED  1024
#define NHEADS 16
#define HDIM   64
#define NB     2
#define NSEQ   2048
#define MTOT   (NB*NSEQ)          // 4096
#define ATTN_SCALE 0.125f         // 1/sqrt(64)

// Scratch (allocation-free rule: __device__ globals)
__device__ float g_Q[NB*NHEADS*NSEQ*HDIM];   // [b,h,n,d]
__device__ float g_K[NB*NHEADS*NSEQ*HDIM];
__device__ float g_V[NB*NHEADS*NSEQ*HDIM];
__device__ float g_AO[MTOT*EMBED];           // attention out, [b*n, e]

// ---------------------------------------------------------------------------
// Generic SGEMM: C[M,N] = A[M,K] @ B[K,N] + bias
// BM=BN=128, BK=16, 256 threads, 8x8 microtile with tx/ty-strided mapping
// MODE 0: QKV projection -> scatter into g_Q/g_K/g_V (head-major)
// MODE 1: plain output (A ignored, reads g_AO) -> C
// ---------------------------------------------------------------------------
template<int MODE>
__global__ __launch_bounds__(256) void sgemm_kernel(
    const float* __restrict__ A_, const float* __restrict__ Bg,
    const float* __restrict__ bias, float* __restrict__ C,
    int M, int N, int K)
{
    const float* A = (MODE == 1) ? g_AO : A_;

    __shared__ float As[16][129];   // [k][m], padded (reads are broadcast)
    __shared__ float Bs[16][128];   // [k][n], stride 128 conflict-free for tx-strided reads

    const int tid = threadIdx.x;
    const int tx  = tid & 15;
    const int ty  = tid >> 4;
    const int m0  = blockIdx.y * 128;
    const int n0  = blockIdx.x * 128;

    float acc[8][8];
#pragma unroll
    for (int i = 0; i < 8; i++)
#pragma unroll
        for (int j = 0; j < 8; j++) acc[i][j] = 0.f;

    for (int k0 = 0; k0 < K; k0 += 16) {
        // Load A tile 128x16 (transposed into As[k][m])
#pragma unroll
        for (int p = 0; p < 2; p++) {
            int f  = tid + p * 256;          // 0..511 float4s
            int m  = f >> 2;
            int c4 = (f & 3) * 4;
            float4 v = *(const float4*)(A + (size_t)(m0 + m) * K + k0 + c4);
            As[c4 + 0][m] = v.x;
            As[c4 + 1][m] = v.y;
            As[c4 + 2][m] = v.z;
            As[c4 + 3][m] = v.w;
        }
        // Load B tile 16x128
#pragma unroll
        for (int p = 0; p < 2; p++) {
            int f  = tid + p * 256;
            int kr = f >> 5;
            int n4 = (f & 31) * 4;
            *(float4*)&Bs[kr][n4] =
                *(const float4*)(Bg + (size_t)(k0 + kr) * N + n0 + n4);
        }
        __syncthreads();

#pragma unroll
        for (int k = 0; k < 16; k++) {
            float a[8], b[8];
#pragma unroll
            for (int i = 0; i < 8; i++) a[i] = As[k][ty + 16 * i];
#pragma unroll
            for (int j = 0; j < 8; j++) b[j] = Bs[k][tx + 16 * j];
#pragma unroll
            for (int i = 0; i < 8; i++)
#pragma unroll
                for (int j = 0; j < 8; j++)
                    acc[i][j] = fmaf(a[i], b[j], acc[i][j]);
        }
        __syncthreads();
    }

    if (MODE == 1) {
#pragma unroll
        for (int i = 0; i < 8; i++) {
            int m = m0 + ty + 16 * i;
#pragma unroll
            for (int j = 0; j < 8; j++) {
                int n = n0 + tx + 16 * j;
                C[(size_t)m * N + n] = acc[i][j] + bias[n];
            }
        }
    } else {
        // scatter into head-major Q/K/V
#pragma unroll
        for (int j = 0; j < 8; j++) {
            int c     = n0 + tx + 16 * j;       // 0..3071
            int which = c >> 10;                // 0=Q 1=K 2=V
            int e     = c & 1023;
            int h     = e >> 6;
            int d     = e & 63;
            float* dst = (which == 0) ? g_Q : (which == 1) ? g_K : g_V;
            float bv = bias[c];
#pragma unroll
            for (int i = 0; i < 8; i++) {
                int m  = m0 + ty + 16 * i;
                int b  = m >> 11;               // /2048
                int nn = m & 2047;
                dst[(((size_t)(b * NHEADS + h)) * NSEQ + nn) * HDIM + d] =
                    acc[i][j] + bv;
            }
        }
    }
}

// ---------------------------------------------------------------------------
// Flash attention: one block = (bh, 64 q-rows). 256 threads, 4x4 microtiles.
// Online softmax over 32 kv-tiles of 64. smem = 48KB exactly (static).
// ---------------------------------------------------------------------------
__global__ __launch_bounds__(256) void flash_kernel(float* __restrict__ AO)
{
    __shared__ float Qs[64 * 64];   // [r][k] linear, float4-friendly
    __shared__ float Ks[64 * 64];   // [c][k] XOR-swizzled; reused as P [r][c]
    __shared__ float Vs[64 * 64];   // [c][d] stride 64

    const int tid = threadIdx.x;
    const int tx  = tid & 15;
    const int ty  = tid >> 4;
    const int mt  = blockIdx.x;          // q tile (0..31)
    const int bh  = blockIdx.y;          // 0..31

    const float* Qg = g_Q + ((size_t)bh * NSEQ + mt * 64) * HDIM;
    const float* Kg = g_K + (size_t)bh * NSEQ * HDIM;
    const float* Vg = g_V + (size_t)bh * NSEQ * HDIM;

    // Load Q tile once, pre-scaled
#pragma unroll
    for (int p = 0; p < 4; p++) {
        int f = tid + p * 256;           // 0..1023 float4s
        float4 v = ((const float4*)Qg)[f];
        v.x *= ATTN_SCALE; v.y *= ATTN_SCALE; v.z *= ATTN_SCALE; v.w *= ATTN_SCALE;
        ((float4*)Qs)[f] = v;
    }

    float m_i[4], l_i[4], o[4][4];
#pragma unroll
    for (int i = 0; i < 4; i++) {
        m_i[i] = -1e30f;
        l_i[i] = 0.f;
#pragma unroll
        for (int j = 0; j < 4; j++) o[i][j] = 0.f;
    }

    for (int t = 0; t < NSEQ / 64; t++) {
        const float4* Kt = (const float4*)(Kg + (size_t)t * 64 * HDIM);
        const float4* Vt = (const float4*)(Vg + (size_t)t * 64 * HDIM);
#pragma unroll
        for (int p = 0; p < 4; p++) {
            int f  = tid + p * 256;
            int r  = f >> 4;
            int c4 = f & 15;
            ((float4*)Ks)[r * 16 + (c4 ^ (r & 7))] = Kt[f];  // swizzled
            ((float4*)Vs)[f] = Vt[f];
        }
        __syncthreads();

        // S = Q @ K^T  (4x4 per thread; rows ty+16i, cols tx+16j)
        float s[4][4];
#pragma unroll
        for (int i = 0; i < 4; i++)
#pragma unroll
            for (int j = 0; j < 4; j++) s[i][j] = 0.f;

#pragma unroll
        for (int k4 = 0; k4 < 16; k4++) {
            float4 q[4], kk[4];
#pragma unroll
            for (int i = 0; i < 4; i++)
                q[i] = ((const float4*)Qs)[(ty + 16 * i) * 16 + k4];
#pragma unroll
            for (int j = 0; j < 4; j++) {
                int r = tx + 16 * j;
                kk[j] = ((const float4*)Ks)[r * 16 + (k4 ^ (r & 7))];
            }
#pragma unroll
            for (int i = 0; i < 4; i++)
#pragma unroll
                for (int j = 0; j < 4; j++) {
                    s[i][j] = fmaf(q[i].x, kk[j].x, s[i][j]);
                    s[i][j] = fmaf(q[i].y, kk[j].y, s[i][j]);
                    s[i][j] = fmaf(q[i].z, kk[j].z, s[i][j]);
                    s[i][j] = fmaf(q[i].w, kk[j].w, s[i][j]);
                }
        }
        __syncthreads();   // everyone done reading Ks before it becomes P

        // Online softmax; write P into Ks buffer (unswizzled [r][c], stride 64)
#pragma unroll
        for (int i = 0; i < 4; i++) {
            float mx = fmaxf(fmaxf(s[i][0], s[i][1]), fmaxf(s[i][2], s[i][3]));
#pragma unroll
            for (int off = 8; off >= 1; off >>= 1)
                mx = fmaxf(mx, __shfl_xor_sync(0xffffffffu, mx, off));
            float mnew = fmaxf(m_i[i], mx);
            float corr = __expf(m_i[i] - mnew);
            float sum = 0.f;
#pragma unroll
            for (int j = 0; j < 4; j++) {
                float pv = __expf(s[i][j] - mnew);
                sum += pv;
                Ks[(ty + 16 * i) * 64 + tx + 16 * j] = pv;
            }
#pragma unroll
            for (int off = 8; off >= 1; off >>= 1)
                sum += __shfl_xor_sync(0xffffffffu, sum, off);
            l_i[i] = l_i[i] * corr + sum;
            m_i[i] = mnew;
#pragma unroll
            for (int j = 0; j < 4; j++) o[i][j] *= corr;
        }
        __syncthreads();   // P visible to all

        // O += P @ V   (c unrolled by 4; P read as float4 broadcast)
#pragma unroll
        for (int c4 = 0; c4 < 16; c4++) {
            float4 p[4];
#pragma unroll
            for (int i = 0; i < 4; i++)
                p[i] = *(const float4*)&Ks[(ty + 16 * i) * 64 + c4 * 4];
#pragma unroll
            for (int cc = 0; cc < 4; cc++) {
                float v[4];
#pragma unroll
                for (int j = 0; j < 4; j++)
                    v[j] = Vs[(c4 * 4 + cc) * 64 + tx + 16 * j];
                float pc;
#pragma unroll
                for (int i = 0; i < 4; i++) {
                    pc = (cc == 0) ? p[i].x : (cc == 1) ? p[i].y
                       : (cc == 2) ? p[i].z : p[i].w;
#pragma unroll
                    for (int j = 0; j < 4; j++)
                        o[i][j] = fmaf(pc, v[j], o[i][j]);
                }
            }
        }
        __syncthreads();   // before next tile overwrites Ks/Vs
    }

    // Normalize and write to [B, N, E]
    const int b = bh >> 4, h = bh & 15;
#pragma unroll
    for (int i = 0; i < 4; i++) {
        float inv = __fdividef(1.f, l_i[i]);
        int n = mt * 64 + ty + 16 * i;
        float* dst = AO + ((size_t)(b * NSEQ + n)) * EMBED + h * HDIM;
#pragma unroll
        for (int j = 0; j < 4; j++)
            dst[tx + 16 * j] = o[i][j] * inv;
    }
}

// ---------------------------------------------------------------------------
extern "C" void kernel_launch(void* const* d_in, const int* in_sizes, int n_in,
                              void* d_out, int out_size)
{
    const float* x     = (const float*)d_in[0];   // [2,2048,1024]
    const float* W_qkv = (const float*)d_in[1];   // [1024,3072]
    const float* b_qkv = (const float*)d_in[2];   // [3072]
    const float* W_out = (const float*)d_in[3];   // [1024,1024]
    const float* b_out = (const float*)d_in[4];   // [1024]
    float* out = (float*)d_out;                   // [2,2048,1024]

    float* ao = nullptr;
    cudaGetSymbolAddress((void**)&ao, g_AO);

    // 1) QKV projection -> g_Q/g_K/g_V (head-major)
    {
        dim3 grid(3072 / 128, MTOT / 128);
        sgemm_kernel<0><<<grid, 256>>>(x, W_qkv, b_qkv, nullptr,
                                       MTOT, 3 * EMBED, EMBED);
    }
    // 2) Flash attention -> g_AO ([B,N,E])
    {
        dim3 grid(NSEQ / 64, NB * NHEADS);
        flash_kernel<<<grid, 256>>>(ao);
    }
    // 3) Output projection -> d_out
    {
        dim3 grid(EMBED / 128, MTOT / 128);
        sgemm_kernel<1><<<grid, 256>>>(nullptr, W_out, b_out, out,
                                       MTOT, EMBED, EMBED);
    }
}

// round 3
// speedup vs baseline: 1.4964x; 1.4964x over previous
#include <cuda_runtime.h>
#include <cuda_bf16.h>
#include <cstdint>
#include <math.h>

#define EMBED  1024
#define NHEADS 16
#define HDIM   64
#define NB     2
#define NSEQ   2048
#define MTOT   (NB*NSEQ)          // 4096
#define GEMM_K 1024
#define ATTN_SCALE 0.125f

// ---------------- scratch (__device__ globals, allocation-free rule) -------
__device__ float g_Q[NB*NHEADS*NSEQ*HDIM];
__device__ float g_K[NB*NHEADS*NSEQ*HDIM];
__device__ float g_V[NB*NHEADS*NSEQ*HDIM];
__device__ float g_AO[MTOT*EMBED];
__device__ float g_Wt_qkv[3*EMBED*EMBED];   // W_qkv^T  [3072][1024]
__device__ float g_Wt_out[EMBED*EMBED];     // W_out^T  [1024][1024]

// ---------------- helpers ---------------------------------------------------
__device__ __forceinline__ uint32_t smem_u32(const void* p) {
    uint32_t a;
    asm("{ .reg .u64 t; cvta.to.shared.u64 t, %1; cvt.u32.u64 %0, t; }"
        : "=r"(a) : "l"(p));
    return a;
}
__device__ __forceinline__ void ldsm4(uint32_t addr, uint32_t* r) {
    asm volatile("ldmatrix.sync.aligned.m8n8.x4.shared.b16 {%0,%1,%2,%3}, [%4];"
        : "=r"(r[0]), "=r"(r[1]), "=r"(r[2]), "=r"(r[3]) : "r"(addr));
}
__device__ __forceinline__ void mma_bf16(float* d, const uint32_t* a, const uint32_t* b) {
    asm volatile(
        "mma.sync.aligned.m16n8k16.row.col.f32.bf16.bf16.f32 "
        "{%0,%1,%2,%3},{%4,%5,%6,%7},{%8,%9},{%0,%1,%2,%3};"
        : "+f"(d[0]), "+f"(d[1]), "+f"(d[2]), "+f"(d[3])
        : "r"(a[0]), "r"(a[1]), "r"(a[2]), "r"(a[3]), "r"(b[0]), "r"(b[1]));
}
__device__ __forceinline__ uint32_t bits_bf162(__nv_bfloat162 h) {
    return *reinterpret_cast<uint32_t*>(&h);
}

// ---------------------------------------------------------------------------
// Weight transpose: src[K][N] row-major -> dst[N][K] row-major
// ---------------------------------------------------------------------------
__global__ void transpose_kernel(const float* __restrict__ S, float* __restrict__ D,
                                 int K, int N)
{
    __shared__ float t[32][33];
    int bx = blockIdx.x * 32;
    int by = blockIdx.y * 32;
    int tx = threadIdx.x, ty = threadIdx.y;
#pragma unroll
    for (int j = 0; j < 32; j += 8)
        t[ty + j][tx] = S[(size_t)(by + ty + j) * N + bx + tx];
    __syncthreads();
#pragma unroll
    for (int j = 0; j < 32; j += 8)
        D[(size_t)(bx + ty + j) * K + by + tx] = t[tx][ty + j];
}

// ---------------------------------------------------------------------------
// mma.sync bf16-split GEMM: C[M,N] = A[M,1024] @ Bt[N,1024]^T + bias
// CTA 128x128, BK=16, 256 thr (8 warps of 64x32), double-buffered static smem.
// bf16 2-way split: hi = trunc16(x), lo = rn_bf16(x - hi); D = AhBh + AhBl + AlBh
// MODE 0: scatter into g_Q/g_K/g_V head-major    MODE 1: A = g_AO, plain C
// ---------------------------------------------------------------------------
// smem tile: 128 rows x 16 bf16 (32B/row); 16B-chunk swizzle: c ^= (row>>2)&1
__device__ __forceinline__ uint32_t tile_off(int r, int chunk) {
    return (uint32_t)(r * 32 + ((chunk ^ ((r >> 2) & 1)) << 4));
}

template<int MODE>
__global__ __launch_bounds__(256, 1) void mma_gemm_kernel(
    const float* __restrict__ A_, const float* __restrict__ Bt,
    const float* __restrict__ bias, float* __restrict__ C, int Nfull)
{
    __shared__ __align__(16) uint8_t smA[2][2][128 * 32];  // [buf][hi/lo]
    __shared__ __align__(16) uint8_t smB[2][2][128 * 32];

    const float* A = (MODE == 1) ? g_AO : A_;
    const int tid  = threadIdx.x;
    const int lane = tid & 31;
    const int wid  = tid >> 5;
    const int wm   = wid >> 2;       // 0..1  (m dim, 64 rows each)
    const int wn   = wid & 3;        // 0..3  (n dim, 32 cols each)
    const int m0   = blockIdx.y * 128;
    const int n0   = blockIdx.x * 128;

    const float* Ag = A  + (size_t)m0 * GEMM_K;
    const float* Bg = Bt + (size_t)n0 * GEMM_K;

    // loader mapping: f in 0..511, r = f>>2 (tile row), c4 = f&3 (float4 in row)
    const int lr0 = tid >> 2, lc0 = tid & 3;        // p = 0
    const int lr1 = (tid + 256) >> 2;               // p = 1 (same c4)

    float acc[4][4][4];
#pragma unroll
    for (int t = 0; t < 4; t++)
#pragma unroll
        for (int u = 0; u < 4; u++)
#pragma unroll
            for (int e = 0; e < 4; e++) acc[t][u][e] = 0.f;

    // convert one float4 -> hi/lo bf16x4 and store to smem
    auto cvt_store = [&](uint8_t* hiB, uint8_t* loB, int r, int c4, float4 v) {
        uint32_t ux = __float_as_uint(v.x), uy = __float_as_uint(v.y);
        uint32_t uz = __float_as_uint(v.z), uw = __float_as_uint(v.w);
        uint32_t h01 = (ux >> 16) | (uy & 0xffff0000u);
        uint32_t h23 = (uz >> 16) | (uw & 0xffff0000u);
        float lx = v.x - __uint_as_float(ux & 0xffff0000u);
        float ly = v.y - __uint_as_float(uy & 0xffff0000u);
        float lz = v.z - __uint_as_float(uz & 0xffff0000u);
        float lw = v.w - __uint_as_float(uw & 0xffff0000u);
        uint32_t l01 = bits_bf162(__floats2bfloat162_rn(lx, ly));
        uint32_t l23 = bits_bf162(__floats2bfloat162_rn(lz, lw));
        uint32_t off = (uint32_t)(r * 32) +
                       (((uint32_t)((c4 >> 1) ^ ((r >> 2) & 1)) << 4) | ((uint32_t)(c4 & 1) << 3));
        *(uint2*)(hiB + off) = make_uint2(h01, h23);
        *(uint2*)(loB + off) = make_uint2(l01, l23);
    };

    float4 pa0, pa1, pb0, pb1;
    // prologue: tile 0
    pa0 = *(const float4*)(Ag + (size_t)lr0 * GEMM_K + lc0 * 4);
    pa1 = *(const float4*)(Ag + (size_t)lr1 * GEMM_K + lc0 * 4);
    pb0 = *(const float4*)(Bg + (size_t)lr0 * GEMM_K + lc0 * 4);
    pb1 = *(const float4*)(Bg + (size_t)lr1 * GEMM_K + lc0 * 4);
    cvt_store(smA[0][0], smA[0][1], lr0, lc0, pa0);
    cvt_store(smA[0][0], smA[0][1], lr1, lc0, pa1);
    cvt_store(smB[0][0], smB[0][1], lr0, lc0, pb0);
    cvt_store(smB[0][0], smB[0][1], lr1, lc0, pb1);
    __syncthreads();

    // ldmatrix lane addressing (constant per thread)
    const int arow = wm * 64 + (lane & 15);         // + t*16
    const int achk = lane >> 4;
    const int brow_base = wn * 32 + (lane & 7) + ((lane >> 4) << 3);  // + p*16
    const int bchk = (lane >> 3) & 1;

    for (int it = 0; it < GEMM_K / 16; ++it) {
        const int buf = it & 1;
        const bool more = (it < GEMM_K / 16 - 1);
        if (more) {
            const int k0 = (it + 1) * 16;
            pa0 = *(const float4*)(Ag + (size_t)lr0 * GEMM_K + k0 + lc0 * 4);
            pa1 = *(const float4*)(Ag + (size_t)lr1 * GEMM_K + k0 + lc0 * 4);
            pb0 = *(const float4*)(Bg + (size_t)lr0 * GEMM_K + k0 + lc0 * 4);
            pb1 = *(const float4*)(Bg + (size_t)lr1 * GEMM_K + k0 + lc0 * 4);
        }

        // ---- compute on buf ----
        {
            const uint32_t bAh = smem_u32(smA[buf][0]);
            const uint32_t bAl = smem_u32(smA[buf][1]);
            const uint32_t bBh = smem_u32(smB[buf][0]);
            const uint32_t bBl = smem_u32(smB[buf][1]);

            uint32_t aH[4][4], aL[4][4], bH[8], bL[8];
#pragma unroll
            for (int t = 0; t < 4; t++) {
                const int m = arow + t * 16;
                const uint32_t off = tile_off(m, achk);
                ldsm4(bAh + off, aH[t]);
                ldsm4(bAl + off, aL[t]);
            }
#pragma unroll
            for (int p = 0; p < 2; p++) {
                const int n = brow_base + p * 16;
                const uint32_t off = tile_off(n, bchk);
                ldsm4(bBh + off, &bH[p * 4]);
                ldsm4(bBl + off, &bL[p * 4]);
            }
#pragma unroll
            for (int t = 0; t < 4; t++)
#pragma unroll
                for (int u = 0; u < 4; u++) {
                    const uint32_t* ph = &bH[(u >> 1) * 4 + (u & 1) * 2];
                    const uint32_t* pl = &bL[(u >> 1) * 4 + (u & 1) * 2];
                    mma_bf16(acc[t][u], aH[t], ph);
                    mma_bf16(acc[t][u], aH[t], pl);
                    mma_bf16(acc[t][u], aL[t], ph);
                }
        }

        if (more) {
            const int nb = buf ^ 1;
            cvt_store(smA[nb][0], smA[nb][1], lr0, lc0, pa0);
            cvt_store(smA[nb][0], smA[nb][1], lr1, lc0, pa1);
            cvt_store(smB[nb][0], smB[nb][1], lr0, lc0, pb0);
            cvt_store(smB[nb][0], smB[nb][1], lr1, lc0, pb1);
        }
        __syncthreads();
    }

    // ---- epilogue: acc -> gmem (+bias) ------------------------------------
    const int mwarp = m0 + wm * 64;
    const int nwarp = n0 + wn * 32;
    const int g = lane >> 2, q = lane & 3;
#pragma unroll
    for (int u = 0; u < 4; u++) {
        const int n = nwarp + u * 8 + 2 * q;
        const float2 bv = *(const float2*)(bias + n);
#pragma unroll
        for (int t = 0; t < 4; t++) {
            const int m = mwarp + t * 16 + g;
            float2 v0 = make_float2(acc[t][u][0] + bv.x, acc[t][u][1] + bv.y);
            float2 v1 = make_float2(acc[t][u][2] + bv.x, acc[t][u][3] + bv.y);
            if (MODE == 1) {
                *(float2*)(C + (size_t)m * Nfull + n)       = v0;
                *(float2*)(C + (size_t)(m + 8) * Nfull + n) = v1;
            } else {
                const int which = n >> 10;
                const int e = n & 1023;
                const int h = e >> 6;
                const int d = e & 63;
                float* dst = (which == 0) ? g_Q : (which == 1) ? g_K : g_V;
                const int b  = m >> 11;
                const size_t base = (((size_t)(b * NHEADS + h)) * NSEQ) * HDIM + d;
                *(float2*)(dst + base + (size_t)(m & 2047) * HDIM)       = v0;
                *(float2*)(dst + base + (size_t)((m + 8) & 2047) * HDIM) = v1;
            }
        }
    }
}

// ---------------------------------------------------------------------------
// Flash attention (fp32, identical to round 1): block = (bh, 64 q-rows)
// ---------------------------------------------------------------------------
__global__ __launch_bounds__(256) void flash_kernel(float* __restrict__ AO)
{
    __shared__ float Qs[64 * 64];
    __shared__ float Ks[64 * 64];   // XOR-swizzled K; reused as P
    __shared__ float Vs[64 * 64];

    const int tid = threadIdx.x;
    const int tx  = tid & 15;
    const int ty  = tid >> 4;
    const int mt  = blockIdx.x;
    const int bh  = blockIdx.y;

    const float* Qg = g_Q + ((size_t)bh * NSEQ + mt * 64) * HDIM;
    const float* Kg = g_K + (size_t)bh * NSEQ * HDIM;
    const float* Vg = g_V + (size_t)bh * NSEQ * HDIM;

#pragma unroll
    for (int p = 0; p < 4; p++) {
        int f = tid + p * 256;
        float4 v = ((const float4*)Qg)[f];
        v.x *= ATTN_SCALE; v.y *= ATTN_SCALE; v.z *= ATTN_SCALE; v.w *= ATTN_SCALE;
        ((float4*)Qs)[f] = v;
    }

    float m_i[4], l_i[4], o[4][4];
#pragma unroll
    for (int i = 0; i < 4; i++) {
        m_i[i] = -1e30f; l_i[i] = 0.f;
#pragma unroll
        for (int j = 0; j < 4; j++) o[i][j] = 0.f;
    }

    for (int t = 0; t < NSEQ / 64; t++) {
        const float4* Kt = (const float4*)(Kg + (size_t)t * 64 * HDIM);
        const float4* Vt = (const float4*)(Vg + (size_t)t * 64 * HDIM);
#pragma unroll
        for (int p = 0; p < 4; p++) {
            int f  = tid + p * 256;
            int r  = f >> 4;
            int c4 = f & 15;
            ((float4*)Ks)[r * 16 + (c4 ^ (r & 7))] = Kt[f];
            ((float4*)Vs)[f] = Vt[f];
        }
        __syncthreads();

        float s[4][4];
#pragma unroll
        for (int i = 0; i < 4; i++)
#pragma unroll
            for (int j = 0; j < 4; j++) s[i][j] = 0.f;

#pragma unroll
        for (int k4 = 0; k4 < 16; k4++) {
            float4 q[4], kk[4];
#pragma unroll
            for (int i = 0; i < 4; i++)
                q[i] = ((const float4*)Qs)[(ty + 16 * i) * 16 + k4];
#pragma unroll
            for (int j = 0; j < 4; j++) {
                int r = tx + 16 * j;
                kk[j] = ((const float4*)Ks)[r * 16 + (k4 ^ (r & 7))];
            }
#pragma unroll
            for (int i = 0; i < 4; i++)
#pragma unroll
                for (int j = 0; j < 4; j++) {
                    s[i][j] = fmaf(q[i].x, kk[j].x, s[i][j]);
                    s[i][j] = fmaf(q[i].y, kk[j].y, s[i][j]);
                    s[i][j] = fmaf(q[i].z, kk[j].z, s[i][j]);
                    s[i][j] = fmaf(q[i].w, kk[j].w, s[i][j]);
                }
        }
        __syncthreads();

#pragma unroll
        for (int i = 0; i < 4; i++) {
            float mx = fmaxf(fmaxf(s[i][0], s[i][1]), fmaxf(s[i][2], s[i][3]));
#pragma unroll
            for (int off = 8; off >= 1; off >>= 1)
                mx = fmaxf(mx, __shfl_xor_sync(0xffffffffu, mx, off));
            float mnew = fmaxf(m_i[i], mx);
            float corr = __expf(m_i[i] - mnew);
            float sum = 0.f;
#pragma unroll
            for (int j = 0; j < 4; j++) {
                float pv = __expf(s[i][j] - mnew);
                sum += pv;
                Ks[(ty + 16 * i) * 64 + tx + 16 * j] = pv;
            }
#pragma unroll
            for (int off = 8; off >= 1; off >>= 1)
                sum += __shfl_xor_sync(0xffffffffu, sum, off);
            l_i[i] = l_i[i] * corr + sum;
            m_i[i] = mnew;
#pragma unroll
            for (int j = 0; j < 4; j++) o[i][j] *= corr;
        }
        __syncthreads();

#pragma unroll
        for (int c4 = 0; c4 < 16; c4++) {
            float4 p[4];
#pragma unroll
            for (int i = 0; i < 4; i++)
                p[i] = *(const float4*)&Ks[(ty + 16 * i) * 64 + c4 * 4];
#pragma unroll
            for (int cc = 0; cc < 4; cc++) {
                float v[4];
#pragma unroll
                for (int j = 0; j < 4; j++)
                    v[j] = Vs[(c4 * 4 + cc) * 64 + tx + 16 * j];
#pragma unroll
                for (int i = 0; i < 4; i++) {
                    float pc = (cc == 0) ? p[i].x : (cc == 1) ? p[i].y
                             : (cc == 2) ? p[i].z : p[i].w;
#pragma unroll
                    for (int j = 0; j < 4; j++)
                        o[i][j] = fmaf(pc, v[j], o[i][j]);
                }
            }
        }
        __syncthreads();
    }

    const int b = bh >> 4, h = bh & 15;
#pragma unroll
    for (int i = 0; i < 4; i++) {
        float inv = __fdividef(1.f, l_i[i]);
        int n = mt * 64 + ty + 16 * i;
        float* dst = AO + ((size_t)(b * NSEQ + n)) * EMBED + h * HDIM;
#pragma unroll
        for (int j = 0; j < 4; j++)
            dst[tx + 16 * j] = o[i][j] * inv;
    }
}

// ---------------------------------------------------------------------------
extern "C" void kernel_launch(void* const* d_in, const int* in_sizes, int n_in,
                              void* d_out, int out_size)
{
    const float* x     = (const float*)d_in[0];
    const float* W_qkv = (const float*)d_in[1];
    const float* b_qkv = (const float*)d_in[2];
    const float* W_out = (const float*)d_in[3];
    const float* b_out = (const float*)d_in[4];
    float* out = (float*)d_out;

    float *ao, *wtq, *wto;
    cudaGetSymbolAddress((void**)&ao,  g_AO);
    cudaGetSymbolAddress((void**)&wtq, g_Wt_qkv);
    cudaGetSymbolAddress((void**)&wto, g_Wt_out);

    // 0) transpose weights -> [N][K]
    transpose_kernel<<<dim3(3*EMBED/32, EMBED/32), dim3(32, 8)>>>(W_qkv, wtq, EMBED, 3*EMBED);
    transpose_kernel<<<dim3(EMBED/32,   EMBED/32), dim3(32, 8)>>>(W_out, wto, EMBED, EMBED);

    // 1) QKV projection (bf16-split HMMA) -> g_Q/g_K/g_V head-major
    mma_gemm_kernel<0><<<dim3(3*EMBED/128, MTOT/128), 256>>>(x, wtq, b_qkv, nullptr, 3*EMBED);

    // 2) flash attention -> g_AO
    flash_kernel<<<dim3(NSEQ/64, NB*NHEADS), 256>>>(ao);

    // 3) output projection (bf16-split HMMA) -> d_out
    mma_gemm_kernel<1><<<dim3(EMBED/128, MTOT/128), 256>>>(nullptr, wto, b_out, out, EMBED);
}

// round 4
// speedup vs baseline: 2.8551x; 1.9080x over previous
#include <cuda_runtime.h>
#include <cuda_bf16.h>
#include <cstdint>
#include <math.h>

#define EMBED  1024
#define NHEADS 16
#define HDIM   64
#define NB     2
#define NSEQ   2048
#define MTOT   (NB*NSEQ)          // 4096
#define GEMM_K 1024
#define ATTN_SCALE 0.125f

// ---------------- scratch (__device__ globals, allocation-free rule) -------
__device__ float g_Q[NB*NHEADS*NSEQ*HDIM];
__device__ float g_K[NB*NHEADS*NSEQ*HDIM];
__device__ float g_V[NB*NHEADS*NSEQ*HDIM];
__device__ float g_AO[MTOT*EMBED];
__device__ float g_Wt_qkv[3*EMBED*EMBED];   // W_qkv^T  [3072][1024]
__device__ float g_Wt_out[EMBED*EMBED];     // W_out^T  [1024][1024]

// ---------------- helpers ---------------------------------------------------
__device__ __forceinline__ uint32_t smem_u32(const void* p) {
    uint32_t a;
    asm("{ .reg .u64 t; cvta.to.shared.u64 t, %1; cvt.u32.u64 %0, t; }"
        : "=r"(a) : "l"(p));
    return a;
}
__device__ __forceinline__ void ldsm4(uint32_t addr, uint32_t* r) {
    asm volatile("ldmatrix.sync.aligned.m8n8.x4.shared.b16 {%0,%1,%2,%3}, [%4];"
        : "=r"(r[0]), "=r"(r[1]), "=r"(r[2]), "=r"(r[3]) : "r"(addr));
}
__device__ __forceinline__ void ldsm4t(uint32_t addr, uint32_t* r) {
    asm volatile("ldmatrix.sync.aligned.m8n8.x4.trans.shared.b16 {%0,%1,%2,%3}, [%4];"
        : "=r"(r[0]), "=r"(r[1]), "=r"(r[2]), "=r"(r[3]) : "r"(addr));
}
__device__ __forceinline__ void mma_bf16(float* d, const uint32_t* a, const uint32_t* b) {
    asm volatile(
        "mma.sync.aligned.m16n8k16.row.col.f32.bf16.bf16.f32 "
        "{%0,%1,%2,%3},{%4,%5,%6,%7},{%8,%9},{%0,%1,%2,%3};"
        : "+f"(d[0]), "+f"(d[1]), "+f"(d[2]), "+f"(d[3])
        : "r"(a[0]), "r"(a[1]), "r"(a[2]), "r"(a[3]), "r"(b[0]), "r"(b[1]));
}
__device__ __forceinline__ uint32_t bits_bf162(__nv_bfloat162 h) {
    return *reinterpret_cast<uint32_t*>(&h);
}
// hi = truncate-to-bf16 of (x,y) packed; lo = rn-bf16 of residuals
__device__ __forceinline__ uint32_t hipack(float x, float y) {
    return (__float_as_uint(x) >> 16) | (__float_as_uint(y) & 0xffff0000u);
}
__device__ __forceinline__ uint32_t lopack(float x, float y) {
    float lx = x - __uint_as_float(__float_as_uint(x) & 0xffff0000u);
    float ly = y - __uint_as_float(__float_as_uint(y) & 0xffff0000u);
    return bits_bf162(__floats2bfloat162_rn(lx, ly));
}
// 128B-row swizzle: chunk (16B) XOR row%8
__device__ __forceinline__ uint32_t swz128(int row, int chunk) {
    return (uint32_t)(row * 128 + ((chunk ^ (row & 7)) << 4));
}
// f32x4 -> hi uint2 + lo uint2
__device__ __forceinline__ void cvt_hl(float4 v, uint2& h, uint2& l) {
    h.x = hipack(v.x, v.y); h.y = hipack(v.z, v.w);
    l.x = lopack(v.x, v.y); l.y = lopack(v.z, v.w);
}

// ---------------------------------------------------------------------------
// Weight transpose: src[K][N] row-major -> dst[N][K] row-major
// ---------------------------------------------------------------------------
__global__ void transpose_kernel(const float* __restrict__ S, float* __restrict__ D,
                                 int K, int N)
{
    __shared__ float t[32][33];
    int bx = blockIdx.x * 32;
    int by = blockIdx.y * 32;
    int tx = threadIdx.x, ty = threadIdx.y;
#pragma unroll
    for (int j = 0; j < 32; j += 8)
        t[ty + j][tx] = S[(size_t)(by + ty + j) * N + bx + tx];
    __syncthreads();
#pragma unroll
    for (int j = 0; j < 32; j += 8)
        D[(size_t)(bx + ty + j) * K + by + tx] = t[tx][ty + j];
}

// ---------------------------------------------------------------------------
// mma.sync bf16-split GEMM (unchanged from round 3)
// ---------------------------------------------------------------------------
__device__ __forceinline__ uint32_t tile_off(int r, int chunk) {
    return (uint32_t)(r * 32 + ((chunk ^ ((r >> 2) & 1)) << 4));
}

template<int MODE>
__global__ __launch_bounds__(256, 1) void mma_gemm_kernel(
    const float* __restrict__ A_, const float* __restrict__ Bt,
    const float* __restrict__ bias, float* __restrict__ C, int Nfull)
{
    __shared__ __align__(16) uint8_t smA[2][2][128 * 32];
    __shared__ __align__(16) uint8_t smB[2][2][128 * 32];

    const float* A = (MODE == 1) ? g_AO : A_;
    const int tid  = threadIdx.x;
    const int lane = tid & 31;
    const int wid  = tid >> 5;
    const int wm   = wid >> 2;
    const int wn   = wid & 3;
    const int m0   = blockIdx.y * 128;
    const int n0   = blockIdx.x * 128;

    const float* Ag = A  + (size_t)m0 * GEMM_K;
    const float* Bg = Bt + (size_t)n0 * GEMM_K;

    const int lr0 = tid >> 2, lc0 = tid & 3;
    const int lr1 = (tid + 256) >> 2;

    float acc[4][4][4];
#pragma unroll
    for (int t = 0; t < 4; t++)
#pragma unroll
        for (int u = 0; u < 4; u++)
#pragma unroll
            for (int e = 0; e < 4; e++) acc[t][u][e] = 0.f;

    auto cvt_store = [&](uint8_t* hiB, uint8_t* loB, int r, int c4, float4 v) {
        uint2 h, l;
        cvt_hl(v, h, l);
        uint32_t off = (uint32_t)(r * 32) +
                       (((uint32_t)((c4 >> 1) ^ ((r >> 2) & 1)) << 4) | ((uint32_t)(c4 & 1) << 3));
        *(uint2*)(hiB + off) = h;
        *(uint2*)(loB + off) = l;
    };

    float4 pa0, pa1, pb0, pb1;
    pa0 = *(const float4*)(Ag + (size_t)lr0 * GEMM_K + lc0 * 4);
    pa1 = *(const float4*)(Ag + (size_t)lr1 * GEMM_K + lc0 * 4);
    pb0 = *(const float4*)(Bg + (size_t)lr0 * GEMM_K + lc0 * 4);
    pb1 = *(const float4*)(Bg + (size_t)lr1 * GEMM_K + lc0 * 4);
    cvt_store(smA[0][0], smA[0][1], lr0, lc0, pa0);
    cvt_store(smA[0][0], smA[0][1], lr1, lc0, pa1);
    cvt_store(smB[0][0], smB[0][1], lr0, lc0, pb0);
    cvt_store(smB[0][0], smB[0][1], lr1, lc0, pb1);
    __syncthreads();

    const int arow = wm * 64 + (lane & 15);
    const int achk = lane >> 4;
    const int brow_base = wn * 32 + (lane & 7) + ((lane >> 4) << 3);
    const int bchk = (lane >> 3) & 1;

    for (int it = 0; it < GEMM_K / 16; ++it) {
        const int buf = it & 1;
        const bool more = (it < GEMM_K / 16 - 1);
        if (more) {
            const int k0 = (it + 1) * 16;
            pa0 = *(const float4*)(Ag + (size_t)lr0 * GEMM_K + k0 + lc0 * 4);
            pa1 = *(const float4*)(Ag + (size_t)lr1 * GEMM_K + k0 + lc0 * 4);
            pb0 = *(const float4*)(Bg + (size_t)lr0 * GEMM_K + k0 + lc0 * 4);
            pb1 = *(const float4*)(Bg + (size_t)lr1 * GEMM_K + k0 + lc0 * 4);
        }
        {
            const uint32_t bAh = smem_u32(smA[buf][0]);
            const uint32_t bAl = smem_u32(smA[buf][1]);
            const uint32_t bBh = smem_u32(smB[buf][0]);
            const uint32_t bBl = smem_u32(smB[buf][1]);

            uint32_t aH[4][4], aL[4][4], bH[8], bL[8];
#pragma unroll
            for (int t = 0; t < 4; t++) {
                const int m = arow + t * 16;
                const uint32_t off = tile_off(m, achk);
                ldsm4(bAh + off, aH[t]);
                ldsm4(bAl + off, aL[t]);
            }
#pragma unroll
            for (int p = 0; p < 2; p++) {
                const int n = brow_base + p * 16;
                const uint32_t off = tile_off(n, bchk);
                ldsm4(bBh + off, &bH[p * 4]);
                ldsm4(bBl + off, &bL[p * 4]);
            }
#pragma unroll
            for (int t = 0; t < 4; t++)
#pragma unroll
                for (int u = 0; u < 4; u++) {
                    const uint32_t* ph = &bH[(u >> 1) * 4 + (u & 1) * 2];
                    const uint32_t* pl = &bL[(u >> 1) * 4 + (u & 1) * 2];
                    mma_bf16(acc[t][u], aH[t], ph);
                    mma_bf16(acc[t][u], aH[t], pl);
                    mma_bf16(acc[t][u], aL[t], ph);
                }
        }
        if (more) {
            const int nb = buf ^ 1;
            cvt_store(smA[nb][0], smA[nb][1], lr0, lc0, pa0);
            cvt_store(smA[nb][0], smA[nb][1], lr1, lc0, pa1);
            cvt_store(smB[nb][0], smB[nb][1], lr0, lc0, pb0);
            cvt_store(smB[nb][0], smB[nb][1], lr1, lc0, pb1);
        }
        __syncthreads();
    }

    const int mwarp = m0 + wm * 64;
    const int nwarp = n0 + wn * 32;
    const int g = lane >> 2, q = lane & 3;
#pragma unroll
    for (int u = 0; u < 4; u++) {
        const int n = nwarp + u * 8 + 2 * q;
        const float2 bv = *(const float2*)(bias + n);
#pragma unroll
        for (int t = 0; t < 4; t++) {
            const int m = mwarp + t * 16 + g;
            float2 v0 = make_float2(acc[t][u][0] + bv.x, acc[t][u][1] + bv.y);
            float2 v1 = make_float2(acc[t][u][2] + bv.x, acc[t][u][3] + bv.y);
            if (MODE == 1) {
                *(float2*)(C + (size_t)m * Nfull + n)       = v0;
                *(float2*)(C + (size_t)(m + 8) * Nfull + n) = v1;
            } else {
                const int which = n >> 10;
                const int e = n & 1023;
                const int h = e >> 6;
                const int d = e & 63;
                float* dst = (which == 0) ? g_Q : (which == 1) ? g_K : g_V;
                const int b  = m >> 11;
                const size_t base = (((size_t)(b * NHEADS + h)) * NSEQ) * HDIM + d;
                *(float2*)(dst + base + (size_t)(m & 2047) * HDIM)       = v0;
                *(float2*)(dst + base + (size_t)((m + 8) & 2047) * HDIM) = v1;
            }
        }
    }
}

// ---------------------------------------------------------------------------
// Flash attention v2: mma.sync bf16-split, register-resident P.
// CTA = 128 q-rows (8 warps x 16), kv-tile 64. smem 32KB (Q phase reuses K/V).
// ---------------------------------------------------------------------------
__global__ __launch_bounds__(256, 1) void flash_mma_kernel(float* __restrict__ AO)
{
    __shared__ __align__(16) uint8_t sb[32768];
    uint8_t* Qh = sb;              uint8_t* Ql = sb + 16384;   // Q phase
    uint8_t* Kh = sb;              uint8_t* Kl = sb + 8192;    // KV phase
    uint8_t* Vh = sb + 16384;      uint8_t* Vl = sb + 24576;

    const int tid  = threadIdx.x;
    const int lane = tid & 31;
    const int wid  = tid >> 5;
    const int mt   = blockIdx.x;       // q tile (0..15)
    const int bh   = blockIdx.y;       // 0..31

    const float* Qg = g_Q + ((size_t)bh * NSEQ + mt * 128) * HDIM;
    const float* Kg = g_K + (size_t)bh * NSEQ * HDIM;
    const float* Vg = g_V + (size_t)bh * NSEQ * HDIM;

    // ---- Q load (pre-scaled) -> smem hi/lo, then to A-frags ----------------
#pragma unroll
    for (int p = 0; p < 8; p++) {
        int f = tid + p * 256;           // 0..2047 float4
        int r = f >> 4, c4 = f & 15;
        float4 v = *(const float4*)(Qg + (size_t)r * HDIM + c4 * 4);
        v.x *= ATTN_SCALE; v.y *= ATTN_SCALE; v.z *= ATTN_SCALE; v.w *= ATTN_SCALE;
        uint2 h, l; cvt_hl(v, h, l);
        uint32_t off = swz128(r, c4 >> 1) + ((c4 & 1) << 3);
        *(uint2*)(Qh + off) = h;
        *(uint2*)(Ql + off) = l;
    }
    __syncthreads();

    uint32_t qH[4][4], qL[4][4];
    {
        const uint32_t bh_ = smem_u32(Qh), bl_ = smem_u32(Ql);
        const int row = wid * 16 + (lane & 15);
#pragma unroll
        for (int kc = 0; kc < 4; kc++) {
            const int chunk = 2 * kc + (lane >> 4);
            const uint32_t off = swz128(row, chunk);
            ldsm4(bh_ + off, qH[kc]);
            ldsm4(bl_ + off, qL[kc]);
        }
    }

    float of[8][4];
#pragma unroll
    for (int u = 0; u < 8; u++)
#pragma unroll
        for (int e = 0; e < 4; e++) of[u][e] = 0.f;
    float m0 = -1e30f, m1 = -1e30f, l0 = 0.f, l1 = 0.f;

    // prefetch tile 0
    float4 kpre[4], vpre[4];
#pragma unroll
    for (int i = 0; i < 4; i++) {
        int f = tid + i * 256;               // 0..1023 float4
        int r = f >> 4, c4 = f & 15;
        kpre[i] = *(const float4*)(Kg + (size_t)r * HDIM + c4 * 4);
        vpre[i] = *(const float4*)(Vg + (size_t)r * HDIM + c4 * 4);
    }

    const uint32_t uKh = smem_u32(Kh), uKl = smem_u32(Kl);
    const uint32_t uVh = smem_u32(Vh), uVl = smem_u32(Vl);

    for (int t = 0; t < NSEQ / 64; t++) {
        __syncthreads();                     // prev compute (or Q ldsm) done
#pragma unroll
        for (int i = 0; i < 4; i++) {
            int f = tid + i * 256;
            int r = f >> 4, c4 = f & 15;
            uint32_t off = swz128(r, c4 >> 1) + ((c4 & 1) << 3);
            uint2 h, l;
            cvt_hl(kpre[i], h, l);
            *(uint2*)(Kh + off) = h; *(uint2*)(Kl + off) = l;
            cvt_hl(vpre[i], h, l);
            *(uint2*)(Vh + off) = h; *(uint2*)(Vl + off) = l;
        }
        __syncthreads();

        if (t < NSEQ / 64 - 1) {
            const float* Kn = Kg + (size_t)(t + 1) * 64 * HDIM;
            const float* Vn = Vg + (size_t)(t + 1) * 64 * HDIM;
#pragma unroll
            for (int i = 0; i < 4; i++) {
                int f = tid + i * 256;
                int r = f >> 4, c4 = f & 15;
                kpre[i] = *(const float4*)(Kn + (size_t)r * HDIM + c4 * 4);
                vpre[i] = *(const float4*)(Vn + (size_t)r * HDIM + c4 * 4);
            }
        }

        // ---- S = Q @ K^T (3-term split) -----------------------------------
        float sf[8][4];
#pragma unroll
        for (int u = 0; u < 8; u++)
#pragma unroll
            for (int e = 0; e < 4; e++) sf[u][e] = 0.f;

        const int brow = (lane & 7) + ((lane >> 4) << 3);
        const int bsel = (lane >> 3) & 1;
#pragma unroll
        for (int kc = 0; kc < 4; kc++) {
            uint32_t bb[16];
            const int chunk = 2 * kc + bsel;
#pragma unroll
            for (int nb = 0; nb < 4; nb++)
                ldsm4(uKh + swz128(nb * 16 + brow, chunk), &bb[nb * 4]);
#pragma unroll
            for (int u = 0; u < 8; u++) {
                const uint32_t* bp = &bb[(u >> 1) * 4 + (u & 1) * 2];
                mma_bf16(sf[u], qH[kc], bp);
                mma_bf16(sf[u], qL[kc], bp);
            }
#pragma unroll
            for (int nb = 0; nb < 4; nb++)
                ldsm4(uKl + swz128(nb * 16 + brow, chunk), &bb[nb * 4]);
#pragma unroll
            for (int u = 0; u < 8; u++)
                mma_bf16(sf[u], qH[kc], &bb[(u >> 1) * 4 + (u & 1) * 2]);
        }

        // ---- online softmax (rows g and g+8) ------------------------------
        {
            float mx0 = -1e30f, mx1 = -1e30f;
#pragma unroll
            for (int u = 0; u < 8; u++) {
                mx0 = fmaxf(mx0, fmaxf(sf[u][0], sf[u][1]));
                mx1 = fmaxf(mx1, fmaxf(sf[u][2], sf[u][3]));
            }
            mx0 = fmaxf(mx0, __shfl_xor_sync(0xffffffffu, mx0, 1));
            mx0 = fmaxf(mx0, __shfl_xor_sync(0xffffffffu, mx0, 2));
            mx1 = fmaxf(mx1, __shfl_xor_sync(0xffffffffu, mx1, 1));
            mx1 = fmaxf(mx1, __shfl_xor_sync(0xffffffffu, mx1, 2));

            float mn0 = fmaxf(m0, mx0), mn1 = fmaxf(m1, mx1);
            float c0 = __expf(m0 - mn0), c1 = __expf(m1 - mn1);
            m0 = mn0; m1 = mn1;
            float s0 = 0.f, s1 = 0.f;
#pragma unroll
            for (int u = 0; u < 8; u++) {
                float p0 = __expf(sf[u][0] - mn0);
                float p1 = __expf(sf[u][1] - mn0);
                float p2 = __expf(sf[u][2] - mn1);
                float p3 = __expf(sf[u][3] - mn1);
                s0 += p0 + p1; s1 += p2 + p3;
                sf[u][0] = p0; sf[u][1] = p1; sf[u][2] = p2; sf[u][3] = p3;
            }
            s0 += __shfl_xor_sync(0xffffffffu, s0, 1);
            s0 += __shfl_xor_sync(0xffffffffu, s0, 2);
            s1 += __shfl_xor_sync(0xffffffffu, s1, 1);
            s1 += __shfl_xor_sync(0xffffffffu, s1, 2);
            l0 = l0 * c0 + s0; l1 = l1 * c1 + s1;
#pragma unroll
            for (int u = 0; u < 8; u++) {
                of[u][0] *= c0; of[u][1] *= c0;
                of[u][2] *= c1; of[u][3] *= c1;
            }
        }

        // ---- P frags (register-resident, hi/lo) ---------------------------
        uint32_t pH[4][4], pL[4][4];
#pragma unroll
        for (int kc = 0; kc < 4; kc++) {
            pH[kc][0] = hipack(sf[2*kc][0],   sf[2*kc][1]);
            pH[kc][1] = hipack(sf[2*kc][2],   sf[2*kc][3]);
            pH[kc][2] = hipack(sf[2*kc+1][0], sf[2*kc+1][1]);
            pH[kc][3] = hipack(sf[2*kc+1][2], sf[2*kc+1][3]);
            pL[kc][0] = lopack(sf[2*kc][0],   sf[2*kc][1]);
            pL[kc][1] = lopack(sf[2*kc][2],   sf[2*kc][3]);
            pL[kc][2] = lopack(sf[2*kc+1][0], sf[2*kc+1][1]);
            pL[kc][3] = lopack(sf[2*kc+1][2], sf[2*kc+1][3]);
        }

        // ---- O += P @ V (3-term split; V via ldmatrix.trans) --------------
        const int vrow_l = lane & 15;
        const int vsel   = lane >> 4;
#pragma unroll
        for (int kc = 0; kc < 4; kc++) {
            uint32_t vv[16];
            const int row = 16 * kc + vrow_l;
#pragma unroll
            for (int vp = 0; vp < 4; vp++)
                ldsm4t(uVh + swz128(row, 2 * vp + vsel), &vv[vp * 4]);
#pragma unroll
            for (int u = 0; u < 8; u++) {
                const uint32_t* bp = &vv[(u >> 1) * 4 + (u & 1) * 2];
                mma_bf16(of[u], pH[kc], bp);
                mma_bf16(of[u], pL[kc], bp);
            }
#pragma unroll
            for (int vp = 0; vp < 4; vp++)
                ldsm4t(uVl + swz128(row, 2 * vp + vsel), &vv[vp * 4]);
#pragma unroll
            for (int u = 0; u < 8; u++)
                mma_bf16(of[u], pH[kc], &vv[(u >> 1) * 4 + (u & 1) * 2]);
        }
    }

    // ---- epilogue: normalize, write [B,N,E] --------------------------------
    const float inv0 = __fdividef(1.f, l0);
    const float inv1 = __fdividef(1.f, l1);
    const int b = bh >> 4, h = bh & 15;
    const int g = lane >> 2, q = lane & 3;
    const int nrow = mt * 128 + wid * 16 + g;
    float* base = AO + ((size_t)(b * NSEQ + nrow)) * EMBED + h * HDIM;
#pragma unroll
    for (int u = 0; u < 8; u++) {
        const int col = 8 * u + 2 * q;
        *(float2*)(base + col) =
            make_float2(of[u][0] * inv0, of[u][1] * inv0);
        *(float2*)(base + 8 * EMBED + col) =
            make_float2(of[u][2] * inv1, of[u][3] * inv1);
    }
}

// ---------------------------------------------------------------------------
extern "C" void kernel_launch(void* const* d_in, const int* in_sizes, int n_in,
                              void* d_out, int out_size)
{
    const float* x     = (const float*)d_in[0];
    const float* W_qkv = (const float*)d_in[1];
    const float* b_qkv = (const float*)d_in[2];
    const float* W_out = (const float*)d_in[3];
    const float* b_out = (const float*)d_in[4];
    float* out = (float*)d_out;

    float *ao, *wtq, *wto;
    cudaGetSymbolAddress((void**)&ao,  g_AO);
    cudaGetSymbolAddress((void**)&wtq, g_Wt_qkv);
    cudaGetSymbolAddress((void**)&wto, g_Wt_out);

    transpose_kernel<<<dim3(3*EMBED/32, EMBED/32), dim3(32, 8)>>>(W_qkv, wtq, EMBED, 3*EMBED);
    transpose_kernel<<<dim3(EMBED/32,   EMBED/32), dim3(32, 8)>>>(W_out, wto, EMBED, EMBED);

    mma_gemm_kernel<0><<<dim3(3*EMBED/128, MTOT/128), 256>>>(x, wtq, b_qkv, nullptr, 3*EMBED);

    flash_mma_kernel<<<dim3(NSEQ/128, NB*NHEADS), 256>>>(ao);

    mma_gemm_kernel<1><<<dim3(EMBED/128, MTOT/128), 256>>>(nullptr, wto, b_out, out, EMBED);
}

// round 5
// speedup vs baseline: 3.0922x; 1.0831x over previous
#include <cuda_runtime.h>
#include <cuda_bf16.h>
#include <cstdint>
#include <math.h>

#define EMBED  1024
#define NHEADS 16
#define HDIM   64
#define NB     2
#define NSEQ   2048
#define MTOT   (NB*NSEQ)          // 4096
#define GEMM_K 1024
#define ATTN_SCALE 0.125f

// ---------------- scratch (__device__ globals) ------------------------------
__device__ __nv_bfloat16 g_Xh[MTOT*EMBED],      g_Xl[MTOT*EMBED];
__device__ __nv_bfloat16 g_Wqh[3*EMBED*EMBED],  g_Wql[3*EMBED*EMBED];
__device__ __nv_bfloat16 g_Woh[EMBED*EMBED],    g_Wol[EMBED*EMBED];
__device__ __nv_bfloat16 g_Qh[NB*NHEADS*NSEQ*HDIM], g_Ql[NB*NHEADS*NSEQ*HDIM];
__device__ __nv_bfloat16 g_Kh[NB*NHEADS*NSEQ*HDIM], g_Kl[NB*NHEADS*NSEQ*HDIM];
__device__ __nv_bfloat16 g_Vh[NB*NHEADS*NSEQ*HDIM], g_Vl[NB*NHEADS*NSEQ*HDIM];
__device__ __nv_bfloat16 g_AOh[MTOT*EMBED],     g_AOl[MTOT*EMBED];

// ---------------- helpers ---------------------------------------------------
__device__ __forceinline__ uint32_t smem_u32(const void* p) {
    uint32_t a;
    asm("{ .reg .u64 t; cvta.to.shared.u64 t, %1; cvt.u32.u64 %0, t; }"
        : "=r"(a) : "l"(p));
    return a;
}
__device__ __forceinline__ void ldsm4(uint32_t addr, uint32_t* r) {
    asm volatile("ldmatrix.sync.aligned.m8n8.x4.shared.b16 {%0,%1,%2,%3}, [%4];"
        : "=r"(r[0]), "=r"(r[1]), "=r"(r[2]), "=r"(r[3]) : "r"(addr));
}
__device__ __forceinline__ void ldsm4t(uint32_t addr, uint32_t* r) {
    asm volatile("ldmatrix.sync.aligned.m8n8.x4.trans.shared.b16 {%0,%1,%2,%3}, [%4];"
        : "=r"(r[0]), "=r"(r[1]), "=r"(r[2]), "=r"(r[3]) : "r"(addr));
}
__device__ __forceinline__ void mma_bf16(float* d, const uint32_t* a, const uint32_t* b) {
    asm volatile(
        "mma.sync.aligned.m16n8k16.row.col.f32.bf16.bf16.f32 "
        "{%0,%1,%2,%3},{%4,%5,%6,%7},{%8,%9},{%0,%1,%2,%3};"
        : "+f"(d[0]), "+f"(d[1]), "+f"(d[2]), "+f"(d[3])
        : "r"(a[0]), "r"(a[1]), "r"(a[2]), "r"(a[3]), "r"(b[0]), "r"(b[1]));
}
__device__ __forceinline__ void cp16(uint32_t s, const void* g) {
    asm volatile("cp.async.cg.shared.global [%0], [%1], 16;" :: "r"(s), "l"(g));
}
#define CP_COMMIT() asm volatile("cp.async.commit_group;" ::: "memory")
#define CP_WAIT0()  asm volatile("cp.async.wait_group 0;" ::: "memory")
#define CP_WAIT1()  asm volatile("cp.async.wait_group 1;" ::: "memory")

__device__ __forceinline__ uint32_t bits_bf162(__nv_bfloat162 h) {
    return *reinterpret_cast<uint32_t*>(&h);
}
__device__ __forceinline__ uint32_t hipack(float x, float y) {
    return (__float_as_uint(x) >> 16) | (__float_as_uint(y) & 0xffff0000u);
}
__device__ __forceinline__ uint32_t lopack(float x, float y) {
    float lx = x - __uint_as_float(__float_as_uint(x) & 0xffff0000u);
    float ly = y - __uint_as_float(__float_as_uint(y) & 0xffff0000u);
    return bits_bf162(__floats2bfloat162_rn(lx, ly));
}
__device__ __forceinline__ void cvt_hl(float4 v, uint2& h, uint2& l) {
    h.x = hipack(v.x, v.y); h.y = hipack(v.z, v.w);
    l.x = lopack(v.x, v.y); l.y = lopack(v.z, v.w);
}
// 128B-row swizzle (flash tiles): 16B chunk XOR row%8
__device__ __forceinline__ uint32_t swz128(int row, int chunk) {
    return (uint32_t)(row * 128 + ((chunk ^ (row & 7)) << 4));
}
// 32B-row GEMM tile swizzle: chunk(0/1) XOR (row>>2)&1
__device__ __forceinline__ uint32_t tile_off(int r, int chunk) {
    return (uint32_t)(r * 32 + ((chunk ^ ((r >> 2) & 1)) << 4));
}

// ---------------------------------------------------------------------------
// Pre-kernels: one-time conversions
// ---------------------------------------------------------------------------
__global__ void convert_hl_kernel(const float* __restrict__ S,
                                  __nv_bfloat16* __restrict__ Dh,
                                  __nv_bfloat16* __restrict__ Dl)
{
    int i = blockIdx.x * blockDim.x + threadIdx.x;   // float4 index
    float4 v = ((const float4*)S)[i];
    uint2 h, l; cvt_hl(v, h, l);
    ((uint2*)Dh)[i] = h;
    ((uint2*)Dl)[i] = l;
}

// src[K][N] f32 -> dst[N][K] bf16 hi/lo
__global__ void transpose_hl_kernel(const float* __restrict__ S,
                                    __nv_bfloat16* __restrict__ Dh,
                                    __nv_bfloat16* __restrict__ Dl,
                                    int K, int N)
{
    __shared__ float t[32][33];
    int bx = blockIdx.x * 32;   // N dim
    int by = blockIdx.y * 32;   // K dim
    int tx = threadIdx.x, ty = threadIdx.y;
#pragma unroll
    for (int j = 0; j < 32; j += 8)
        t[ty + j][tx] = S[(size_t)(by + ty + j) * N + bx + tx];
    __syncthreads();
#pragma unroll
    for (int j = 0; j < 32; j += 8) {
        float v = t[tx][ty + j];
        size_t idx = (size_t)(bx + ty + j) * K + by + tx;
        uint32_t u = __float_as_uint(v);
        ((uint16_t*)Dh)[idx] = (uint16_t)(u >> 16);
        float lr = v - __uint_as_float(u & 0xffff0000u);
        __nv_bfloat16 lb = __float2bfloat16(lr);
        ((uint16_t*)Dl)[idx] = *reinterpret_cast<uint16_t*>(&lb);
    }
}

// ---------------------------------------------------------------------------
// bf16-split GEMM, cp.async 3-stage: C = A[M,1024] @ B[N,1024]^T + bias
// MODE 0: scatter Q(scaled)/K/V hi+lo head-major    MODE 1: fp32 C + bias
// ---------------------------------------------------------------------------
template<int MODE>
__global__ __launch_bounds__(256) void gemm_bf16_kernel(
    const __nv_bfloat16* __restrict__ Ah, const __nv_bfloat16* __restrict__ Al,
    const __nv_bfloat16* __restrict__ Bh, const __nv_bfloat16* __restrict__ Bl,
    const float* __restrict__ bias, float* __restrict__ C, int Nfull)
{
    __shared__ __align__(16) uint8_t sm[3 * 16384];   // 3 stages x (Ah,Al,Bh,Bl @4KB)

    const int tid  = threadIdx.x;
    const int lane = tid & 31;
    const int wid  = tid >> 5;
    const int wm   = wid >> 2;
    const int wn   = wid & 3;
    const int m0   = blockIdx.y * 128;
    const int n0   = blockIdx.x * 128;
    const uint32_t uSm = smem_u32(sm);

    const int lr = tid >> 1, lc = tid & 1;
    const uint32_t loff = tile_off(lr, lc);

    auto issue = [&](int buf, int it) {
        const int k0 = it * 16;
        const uint32_t s = uSm + buf * 16384;
        cp16(s + loff,         Ah + (size_t)(m0 + lr) * GEMM_K + k0 + lc * 8);
        cp16(s + 4096 + loff,  Al + (size_t)(m0 + lr) * GEMM_K + k0 + lc * 8);
        cp16(s + 8192 + loff,  Bh + (size_t)(n0 + lr) * GEMM_K + k0 + lc * 8);
        cp16(s + 12288 + loff, Bl + (size_t)(n0 + lr) * GEMM_K + k0 + lc * 8);
    };

    float acc[4][4][4];
#pragma unroll
    for (int t = 0; t < 4; t++)
#pragma unroll
        for (int u = 0; u < 4; u++)
#pragma unroll
            for (int e = 0; e < 4; e++) acc[t][u][e] = 0.f;

    issue(0, 0); CP_COMMIT();
    issue(1, 1); CP_COMMIT();

    const int arow = wm * 64 + (lane & 15);
    const int achk = lane >> 4;
    const int brow_base = wn * 32 + (lane & 7) + ((lane >> 4) << 3);
    const int bchk = (lane >> 3) & 1;

    for (int it = 0; it < GEMM_K / 16; ++it) {
        if (it >= GEMM_K / 16 - 2) { CP_WAIT0(); } else { CP_WAIT1(); }
        __syncthreads();
        if (it + 2 < GEMM_K / 16) { issue((it + 2) % 3, it + 2); CP_COMMIT(); }

        const uint32_t s  = uSm + (it % 3) * 16384;
        const uint32_t bAh = s, bAl = s + 4096, bBh = s + 8192, bBl = s + 12288;

        uint32_t aH[4][4], aL[4][4], bH[8], bL[8];
#pragma unroll
        for (int t = 0; t < 4; t++) {
            const uint32_t off = tile_off(arow + t * 16, achk);
            ldsm4(bAh + off, aH[t]);
            ldsm4(bAl + off, aL[t]);
        }
#pragma unroll
        for (int p = 0; p < 2; p++) {
            const uint32_t off = tile_off(brow_base + p * 16, bchk);
            ldsm4(bBh + off, &bH[p * 4]);
            ldsm4(bBl + off, &bL[p * 4]);
        }
#pragma unroll
        for (int t = 0; t < 4; t++)
#pragma unroll
            for (int u = 0; u < 4; u++) {
                const uint32_t* ph = &bH[(u >> 1) * 4 + (u & 1) * 2];
                const uint32_t* pl = &bL[(u >> 1) * 4 + (u & 1) * 2];
                mma_bf16(acc[t][u], aH[t], ph);
                mma_bf16(acc[t][u], aH[t], pl);
                mma_bf16(acc[t][u], aL[t], ph);
            }
        __syncthreads();
    }

    // ---- epilogue ----------------------------------------------------------
    const int mwarp = m0 + wm * 64;
    const int nwarp = n0 + wn * 32;
    const int g = lane >> 2, q = lane & 3;
#pragma unroll
    for (int u = 0; u < 4; u++) {
        const int n = nwarp + u * 8 + 2 * q;
        const float2 bv = *(const float2*)(bias + n);
#pragma unroll
        for (int t = 0; t < 4; t++) {
            const int m = mwarp + t * 16 + g;
            float2 v0 = make_float2(acc[t][u][0] + bv.x, acc[t][u][1] + bv.y);
            float2 v1 = make_float2(acc[t][u][2] + bv.x, acc[t][u][3] + bv.y);
            if (MODE == 1) {
                *(float2*)(C + (size_t)m * Nfull + n)       = v0;
                *(float2*)(C + (size_t)(m + 8) * Nfull + n) = v1;
            } else {
                const int which = n >> 10;
                const int e = n & 1023;
                const int h = e >> 6;
                const int d = e & 63;
                if (which == 0) { v0.x *= ATTN_SCALE; v0.y *= ATTN_SCALE;
                                  v1.x *= ATTN_SCALE; v1.y *= ATTN_SCALE; }
                __nv_bfloat16* dh = (which == 0) ? g_Qh : (which == 1) ? g_Kh : g_Vh;
                __nv_bfloat16* dl = (which == 0) ? g_Ql : (which == 1) ? g_Kl : g_Vl;
                const int b  = m >> 11;
                const size_t base = (((size_t)(b * NHEADS + h)) * NSEQ) * HDIM + d;
                const size_t o0 = base + (size_t)(m & 2047) * HDIM;
                const size_t o1 = base + (size_t)((m + 8) & 2047) * HDIM;
                *(uint32_t*)(dh + o0) = hipack(v0.x, v0.y);
                *(uint32_t*)(dl + o0) = lopack(v0.x, v0.y);
                *(uint32_t*)(dh + o1) = hipack(v1.x, v1.y);
                *(uint32_t*)(dl + o1) = lopack(v1.x, v1.y);
            }
        }
    }
}

// ---------------------------------------------------------------------------
// Flash attention v3: pure bf16, cp.async 2-stage KV, Q smem-resident.
// 128 q-rows / CTA (8 warps x 16), kv tile 64. Dyn smem 96KB, 2 CTAs/SM.
// ---------------------------------------------------------------------------
#define FLASH_SMEM (32768 + 2*32768)   // Q(hi+lo 32KB) + 2 KV stages (32KB each)

__global__ __launch_bounds__(256, 2) void flash_mma_v3()
{
    extern __shared__ __align__(16) uint8_t sb[];
    const uint32_t uQh = smem_u32(sb);
    const uint32_t uQl = uQh + 16384;

    const int tid  = threadIdx.x;
    const int lane = tid & 31;
    const int wid  = tid >> 5;
    const int mt   = blockIdx.x;       // q tile (0..15)
    const int bh   = blockIdx.y;       // 0..31

    const size_t kvbase = (size_t)bh * NSEQ * HDIM;
    const __nv_bfloat16* Qhg = g_Qh + kvbase + (size_t)mt * 128 * HDIM;
    const __nv_bfloat16* Qlg = g_Ql + kvbase + (size_t)mt * 128 * HDIM;

    // Q load: 128 rows x 8 chunks x (hi,lo)
    {
        const int r = tid >> 1;                 // 0..127
        const int cb = (tid & 1) * 4;           // chunk base 0 or 4
#pragma unroll
        for (int c = 0; c < 4; c++) {
            cp16(uQh + swz128(r, cb + c), Qhg + (size_t)r * HDIM + (cb + c) * 8);
            cp16(uQl + swz128(r, cb + c), Qlg + (size_t)r * HDIM + (cb + c) * 8);
        }
    }

    auto issue_kv = [&](int t, int buf) {
        const uint32_t base = uQh + 32768 + buf * 32768;
        const __nv_bfloat16* Ks_h = g_Kh + kvbase + (size_t)t * 64 * HDIM;
        const __nv_bfloat16* Ks_l = g_Kl + kvbase + (size_t)t * 64 * HDIM;
        const __nv_bfloat16* Vs_h = g_Vh + kvbase + (size_t)t * 64 * HDIM;
        const __nv_bfloat16* Vs_l = g_Vl + kvbase + (size_t)t * 64 * HDIM;
#pragma unroll
        for (int i = 0; i < 2; i++) {
            const int id = tid + i * 256;       // 0..511
            const int r = id >> 3, c = id & 7;
            const uint32_t off = swz128(r, c);
            const size_t src = (size_t)r * HDIM + c * 8;
            cp16(base + off,          Ks_h + src);
            cp16(base + 8192 + off,   Ks_l + src);
            cp16(base + 16384 + off,  Vs_h + src);
            cp16(base + 24576 + off,  Vs_l + src);
        }
    };

    issue_kv(0, 0);
    CP_COMMIT();

    float of[8][4];
#pragma unroll
    for (int u = 0; u < 8; u++)
#pragma unroll
        for (int e = 0; e < 4; e++) of[u][e] = 0.f;
    float m0 = -1e30f, m1 = -1e30f, l0 = 0.f, l1 = 0.f;

    const int qrow = wid * 16 + (lane & 15);
    const int qsel = lane >> 4;
    const int brow = (lane & 7) + ((lane >> 4) << 3);
    const int bsel = (lane >> 3) & 1;
    const int vrow_l = lane & 15;
    const int vsel   = lane >> 4;

    for (int t = 0; t < NSEQ / 64; t++) {
        CP_WAIT0();
        __syncthreads();
        if (t + 1 < NSEQ / 64) { issue_kv(t + 1, (t + 1) & 1); CP_COMMIT(); }

        const uint32_t kvb = uQh + 32768 + (t & 1) * 32768;
        const uint32_t uKh = kvb, uKl = kvb + 8192;
        const uint32_t uVh = kvb + 16384, uVl = kvb + 24576;

        // ---- S = Q @ K^T (3-term) -----------------------------------------
        float sf[8][4];
#pragma unroll
        for (int u = 0; u < 8; u++)
#pragma unroll
            for (int e = 0; e < 4; e++) sf[u][e] = 0.f;

#pragma unroll
        for (int kc = 0; kc < 4; kc++) {
            uint32_t qh[4], ql[4];
            ldsm4(uQh + swz128(qrow, 2 * kc + qsel), qh);
            ldsm4(uQl + swz128(qrow, 2 * kc + qsel), ql);
            uint32_t bb[16];
#pragma unroll
            for (int nb = 0; nb < 4; nb++)
                ldsm4(uKh + swz128(nb * 16 + brow, 2 * kc + bsel), &bb[nb * 4]);
#pragma unroll
            for (int u = 0; u < 8; u++) {
                const uint32_t* bp = &bb[(u >> 1) * 4 + (u & 1) * 2];
                mma_bf16(sf[u], qh, bp);
                mma_bf16(sf[u], ql, bp);
            }
#pragma unroll
            for (int nb = 0; nb < 4; nb++)
                ldsm4(uKl + swz128(nb * 16 + brow, 2 * kc + bsel), &bb[nb * 4]);
#pragma unroll
            for (int u = 0; u < 8; u++)
                mma_bf16(sf[u], qh, &bb[(u >> 1) * 4 + (u & 1) * 2]);
        }

        // ---- online softmax ----------------------------------------------
        {
            float mx0 = -1e30f, mx1 = -1e30f;
#pragma unroll
            for (int u = 0; u < 8; u++) {
                mx0 = fmaxf(mx0, fmaxf(sf[u][0], sf[u][1]));
                mx1 = fmaxf(mx1, fmaxf(sf[u][2], sf[u][3]));
            }
            mx0 = fmaxf(mx0, __shfl_xor_sync(0xffffffffu, mx0, 1));
            mx0 = fmaxf(mx0, __shfl_xor_sync(0xffffffffu, mx0, 2));
            mx1 = fmaxf(mx1, __shfl_xor_sync(0xffffffffu, mx1, 1));
            mx1 = fmaxf(mx1, __shfl_xor_sync(0xffffffffu, mx1, 2));

            float mn0 = fmaxf(m0, mx0), mn1 = fmaxf(m1, mx1);
            float c0 = __expf(m0 - mn0), c1 = __expf(m1 - mn1);
            m0 = mn0; m1 = mn1;
            float s0 = 0.f, s1 = 0.f;
#pragma unroll
            for (int u = 0; u < 8; u++) {
                float p0 = __expf(sf[u][0] - mn0);
                float p1 = __expf(sf[u][1] - mn0);
                float p2 = __expf(sf[u][2] - mn1);
                float p3 = __expf(sf[u][3] - mn1);
                s0 += p0 + p1; s1 += p2 + p3;
                sf[u][0] = p0; sf[u][1] = p1; sf[u][2] = p2; sf[u][3] = p3;
            }
            s0 += __shfl_xor_sync(0xffffffffu, s0, 1);
            s0 += __shfl_xor_sync(0xffffffffu, s0, 2);
            s1 += __shfl_xor_sync(0xffffffffu, s1, 1);
            s1 += __shfl_xor_sync(0xffffffffu, s1, 2);
            l0 = l0 * c0 + s0; l1 = l1 * c1 + s1;
#pragma unroll
            for (int u = 0; u < 8; u++) {
                of[u][0] *= c0; of[u][1] *= c0;
                of[u][2] *= c1; of[u][3] *= c1;
            }
        }

        // ---- P frags (register hi/lo) -------------------------------------
        uint32_t pH[4][4], pL[4][4];
#pragma unroll
        for (int kc = 0; kc < 4; kc++) {
            pH[kc][0] = hipack(sf[2*kc][0],   sf[2*kc][1]);
            pH[kc][1] = hipack(sf[2*kc][2],   sf[2*kc][3]);
            pH[kc][2] = hipack(sf[2*kc+1][0], sf[2*kc+1][1]);
            pH[kc][3] = hipack(sf[2*kc+1][2], sf[2*kc+1][3]);
            pL[kc][0] = lopack(sf[2*kc][0],   sf[2*kc][1]);
            pL[kc][1] = lopack(sf[2*kc][2],   sf[2*kc][3]);
            pL[kc][2] = lopack(sf[2*kc+1][0], sf[2*kc+1][1]);
            pL[kc][3] = lopack(sf[2*kc+1][2], sf[2*kc+1][3]);
        }

        // ---- O += P @ V (3-term; V via ldmatrix.trans) --------------------
#pragma unroll
        for (int kc = 0; kc < 4; kc++) {
            uint32_t vv[16];
            const int row = 16 * kc + vrow_l;
#pragma unroll
            for (int vp = 0; vp < 4; vp++)
                ldsm4t(uVh + swz128(row, 2 * vp + vsel), &vv[vp * 4]);
#pragma unroll
            for (int u = 0; u < 8; u++) {
                const uint32_t* bp = &vv[(u >> 1) * 4 + (u & 1) * 2];
                mma_bf16(of[u], pH[kc], bp);
                mma_bf16(of[u], pL[kc], bp);
            }
#pragma unroll
            for (int vp = 0; vp < 4; vp++)
                ldsm4t(uVl + swz128(row, 2 * vp + vsel), &vv[vp * 4]);
#pragma unroll
            for (int u = 0; u < 8; u++)
                mma_bf16(of[u], pH[kc], &vv[(u >> 1) * 4 + (u & 1) * 2]);
        }
    }

    // ---- epilogue: normalize, write AO as bf16 hi/lo [B*N, E] --------------
    const float inv0 = __fdividef(1.f, l0);
    const float inv1 = __fdividef(1.f, l1);
    const int b = bh >> 4, h = bh & 15;
    const int g = lane >> 2, q = lane & 3;
    const int nrow = mt * 128 + wid * 16 + g;
    const size_t r0 = ((size_t)(b * NSEQ + nrow)) * EMBED + h * HDIM;
    const size_t r1 = r0 + (size_t)8 * EMBED;
#pragma unroll
    for (int u = 0; u < 8; u++) {
        const int col = 8 * u + 2 * q;
        float x0 = of[u][0] * inv0, y0 = of[u][1] * inv0;
        float x1 = of[u][2] * inv1, y1 = of[u][3] * inv1;
        *(uint32_t*)(g_AOh + r0 + col) = hipack(x0, y0);
        *(uint32_t*)(g_AOl + r0 + col) = lopack(x0, y0);
        *(uint32_t*)(g_AOh + r1 + col) = hipack(x1, y1);
        *(uint32_t*)(g_AOl + r1 + col) = lopack(x1, y1);
    }
}

// ---------------------------------------------------------------------------
extern "C" void kernel_launch(void* const* d_in, const int* in_sizes, int n_in,
                              void* d_out, int out_size)
{
    const float* x     = (const float*)d_in[0];
    const float* W_qkv = (const float*)d_in[1];
    const float* b_qkv = (const float*)d_in[2];
    const float* W_out = (const float*)d_in[3];
    const float* b_out = (const float*)d_in[4];
    float* out = (float*)d_out;

    __nv_bfloat16 *xh, *xl, *wqh, *wql, *woh, *wol, *aoh, *aol;
    cudaGetSymbolAddress((void**)&xh,  g_Xh);
    cudaGetSymbolAddress((void**)&xl,  g_Xl);
    cudaGetSymbolAddress((void**)&wqh, g_Wqh);
    cudaGetSymbolAddress((void**)&wql, g_Wql);
    cudaGetSymbolAddress((void**)&woh, g_Woh);
    cudaGetSymbolAddress((void**)&wol, g_Wol);
    cudaGetSymbolAddress((void**)&aoh, g_AOh);
    cudaGetSymbolAddress((void**)&aol, g_AOl);

    cudaFuncSetAttribute(flash_mma_v3,
                         cudaFuncAttributeMaxDynamicSharedMemorySize, FLASH_SMEM);

    // 0) one-time conversions
    convert_hl_kernel<<<(MTOT * EMBED / 4) / 256, 256>>>(x, xh, xl);
    transpose_hl_kernel<<<dim3(3*EMBED/32, EMBED/32), dim3(32, 8)>>>(W_qkv, wqh, wql, EMBED, 3*EMBED);
    transpose_hl_kernel<<<dim3(EMBED/32,   EMBED/32), dim3(32, 8)>>>(W_out, woh, wol, EMBED, EMBED);

    // 1) QKV projection -> Q(scaled)/K/V bf16 hi/lo head-major
    gemm_bf16_kernel<0><<<dim3(3*EMBED/128, MTOT/128), 256>>>(
        xh, xl, wqh, wql, b_qkv, nullptr, 3*EMBED);

    // 2) flash attention -> AO bf16 hi/lo
    flash_mma_v3<<<dim3(NSEQ/128, NB*NHEADS), 256, FLASH_SMEM>>>();

    // 3) output projection -> d_out (fp32)
    gemm_bf16_kernel<1><<<dim3(EMBED/128, MTOT/128), 256>>>(
        aoh, aol, woh, wol, b_out, out, EMBED);
}

// round 7
// speedup vs baseline: 3.0956x; 1.0011x over previous
#include <cuda_runtime.h>
#include <cuda_bf16.h>
#include <cstdint>
#include <math.h>

#define EMBED  1024
#define NHEADS 16
#define HDIM   64
#define NB     2
#define NSEQ   2048
#define MTOT   (NB*NSEQ)          // 4096
#define GEMM_K 1024
#define ATTN_SCALE 0.125f

// ---------------- scratch (__device__ globals) ------------------------------
__device__ __nv_bfloat16 g_Xh[MTOT*EMBED],      g_Xl[MTOT*EMBED];
__device__ __nv_bfloat16 g_Wqh[3*EMBED*EMBED],  g_Wql[3*EMBED*EMBED];
__device__ __nv_bfloat16 g_Woh[EMBED*EMBED],    g_Wol[EMBED*EMBED];
__device__ __nv_bfloat16 g_Qh[NB*NHEADS*NSEQ*HDIM], g_Ql[NB*NHEADS*NSEQ*HDIM];
__device__ __nv_bfloat16 g_Kh[NB*NHEADS*NSEQ*HDIM], g_Kl[NB*NHEADS*NSEQ*HDIM];
__device__ __nv_bfloat16 g_Vh[NB*NHEADS*NSEQ*HDIM], g_Vl[NB*NHEADS*NSEQ*HDIM];
__device__ __nv_bfloat16 g_AOh[MTOT*EMBED],     g_AOl[MTOT*EMBED];

// ---------------- helpers ---------------------------------------------------
__device__ __forceinline__ uint32_t smem_u32(const void* p) {
    uint32_t a;
    asm("{ .reg .u64 t; cvta.to.shared.u64 t, %1; cvt.u32.u64 %0, t; }"
        : "=r"(a) : "l"(p));
    return a;
}
__device__ __forceinline__ void ldsm4(uint32_t addr, uint32_t* r) {
    asm volatile("ldmatrix.sync.aligned.m8n8.x4.shared.b16 {%0,%1,%2,%3}, [%4];"
        : "=r"(r[0]), "=r"(r[1]), "=r"(r[2]), "=r"(r[3]) : "r"(addr));
}
__device__ __forceinline__ void ldsm4t(uint32_t addr, uint32_t* r) {
    asm volatile("ldmatrix.sync.aligned.m8n8.x4.trans.shared.b16 {%0,%1,%2,%3}, [%4];"
        : "=r"(r[0]), "=r"(r[1]), "=r"(r[2]), "=r"(r[3]) : "r"(addr));
}
__device__ __forceinline__ void mma_bf16(float* d, const uint32_t* a, const uint32_t* b) {
    asm volatile(
        "mma.sync.aligned.m16n8k16.row.col.f32.bf16.bf16.f32 "
        "{%0,%1,%2,%3},{%4,%5,%6,%7},{%8,%9},{%0,%1,%2,%3};"
        : "+f"(d[0]), "+f"(d[1]), "+f"(d[2]), "+f"(d[3])
        : "r"(a[0]), "r"(a[1]), "r"(a[2]), "r"(a[3]), "r"(b[0]), "r"(b[1]));
}
__device__ __forceinline__ void cp16(uint32_t s, const void* g) {
    asm volatile("cp.async.cg.shared.global [%0], [%1], 16;" :: "r"(s), "l"(g));
}
#define CP_COMMIT() asm volatile("cp.async.commit_group;" ::: "memory")
#define CP_WAIT0()  asm volatile("cp.async.wait_group 0;" ::: "memory")
#define CP_WAIT1()  asm volatile("cp.async.wait_group 1;" ::: "memory")

__device__ __forceinline__ uint32_t bits_bf162(__nv_bfloat162 h) {
    return *reinterpret_cast<uint32_t*>(&h);
}
__device__ __forceinline__ uint32_t hipack(float x, float y) {
    return (__float_as_uint(x) >> 16) | (__float_as_uint(y) & 0xffff0000u);
}
__device__ __forceinline__ uint32_t lopack(float x, float y) {
    float lx = x - __uint_as_float(__float_as_uint(x) & 0xffff0000u);
    float ly = y - __uint_as_float(__float_as_uint(y) & 0xffff0000u);
    return bits_bf162(__floats2bfloat162_rn(lx, ly));
}
__device__ __forceinline__ void cvt_hl(float4 v, uint2& h, uint2& l) {
    h.x = hipack(v.x, v.y); h.y = hipack(v.z, v.w);
    l.x = lopack(v.x, v.y); l.y = lopack(v.z, v.w);
}
// 128B-row swizzle (flash tiles): 16B chunk XOR row%8
__device__ __forceinline__ uint32_t swz128(int row, int chunk) {
    return (uint32_t)(row * 128 + ((chunk ^ (row & 7)) << 4));
}
// 32B-row GEMM tile swizzle: chunk(0/1) XOR (row>>2)&1
__device__ __forceinline__ uint32_t tile_off(int r, int chunk) {
    return (uint32_t)(r * 32 + ((chunk ^ ((r >> 2) & 1)) << 4));
}

// ---------------------------------------------------------------------------
// Pre-kernels: one-time conversions
// ---------------------------------------------------------------------------
__global__ void convert_hl_kernel(const float* __restrict__ S,
                                  __nv_bfloat16* __restrict__ Dh,
                                  __nv_bfloat16* __restrict__ Dl)
{
    int i = blockIdx.x * blockDim.x + threadIdx.x;   // float4 index
    float4 v = ((const float4*)S)[i];
    uint2 h, l; cvt_hl(v, h, l);
    ((uint2*)Dh)[i] = h;
    ((uint2*)Dl)[i] = l;
}

// src[K][N] f32 -> dst[N][K] bf16 hi/lo
__global__ void transpose_hl_kernel(const float* __restrict__ S,
                                    __nv_bfloat16* __restrict__ Dh,
                                    __nv_bfloat16* __restrict__ Dl,
                                    int K, int N)
{
    __shared__ float t[32][33];
    int bx = blockIdx.x * 32;   // N dim
    int by = blockIdx.y * 32;   // K dim
    int tx = threadIdx.x, ty = threadIdx.y;
#pragma unroll
    for (int j = 0; j < 32; j += 8)
        t[ty + j][tx] = S[(size_t)(by + ty + j) * N + bx + tx];
    __syncthreads();
#pragma unroll
    for (int j = 0; j < 32; j += 8) {
        float v = t[tx][ty + j];
        size_t idx = (size_t)(bx + ty + j) * K + by + tx;
        uint32_t u = __float_as_uint(v);
        ((uint16_t*)Dh)[idx] = (uint16_t)(u >> 16);
        float lr = v - __uint_as_float(u & 0xffff0000u);
        __nv_bfloat16 lb = __float2bfloat16(lr);
        ((uint16_t*)Dl)[idx] = *reinterpret_cast<uint16_t*>(&lb);
    }
}

// ---------------------------------------------------------------------------
// bf16-split GEMM, cp.async 3-stage: C = A[M,1024] @ B[N,1024]^T + bias
// MMAs issued TERM-MAJOR: 16 independent accumulators between same-acc reuse.
// MODE 0: scatter Q(scaled)/K/V hi+lo head-major    MODE 1: fp32 C + bias
// ---------------------------------------------------------------------------
template<int MODE>
__global__ __launch_bounds__(256) void gemm_bf16_kernel(
    const __nv_bfloat16* __restrict__ Ah, const __nv_bfloat16* __restrict__ Al,
    const __nv_bfloat16* __restrict__ Bh, const __nv_bfloat16* __restrict__ Bl,
    const float* __restrict__ bias, float* __restrict__ C, int Nfull)
{
    __shared__ __align__(16) uint8_t sm[3 * 16384];   // 3 stages x (Ah,Al,Bh,Bl @4KB)

    const int tid  = threadIdx.x;
    const int lane = tid & 31;
    const int wid  = tid >> 5;
    const int wm   = wid >> 2;
    const int wn   = wid & 3;
    const int m0   = blockIdx.y * 128;
    const int n0   = blockIdx.x * 128;
    const uint32_t uSm = smem_u32(sm);

    const int lr = tid >> 1, lc = tid & 1;
    const uint32_t loff = tile_off(lr, lc);

    auto issue = [&](int buf, int it) {
        const int k0 = it * 16;
        const uint32_t s = uSm + buf * 16384;
        cp16(s + loff,         Ah + (size_t)(m0 + lr) * GEMM_K + k0 + lc * 8);
        cp16(s + 4096 + loff,  Al + (size_t)(m0 + lr) * GEMM_K + k0 + lc * 8);
        cp16(s + 8192 + loff,  Bh + (size_t)(n0 + lr) * GEMM_K + k0 + lc * 8);
        cp16(s + 12288 + loff, Bl + (size_t)(n0 + lr) * GEMM_K + k0 + lc * 8);
    };

    float acc[4][4][4];
#pragma unroll
    for (int t = 0; t < 4; t++)
#pragma unroll
        for (int u = 0; u < 4; u++)
#pragma unroll
            for (int e = 0; e < 4; e++) acc[t][u][e] = 0.f;

    issue(0, 0); CP_COMMIT();
    issue(1, 1); CP_COMMIT();

    const int arow = wm * 64 + (lane & 15);
    const int achk = lane >> 4;
    const int brow_base = wn * 32 + (lane & 7) + ((lane >> 4) << 3);
    const int bchk = (lane >> 3) & 1;

    for (int it = 0; it < GEMM_K / 16; ++it) {
        if (it >= GEMM_K / 16 - 2) { CP_WAIT0(); } else { CP_WAIT1(); }
        __syncthreads();
        if (it + 2 < GEMM_K / 16) { issue((it + 2) % 3, it + 2); CP_COMMIT(); }

        const uint32_t s  = uSm + (it % 3) * 16384;
        const uint32_t bAh = s, bAl = s + 4096, bBh = s + 8192, bBl = s + 12288;

        uint32_t aH[4][4], aL[4][4], bH[8], bL[8];
#pragma unroll
        for (int t = 0; t < 4; t++) {
            const uint32_t off = tile_off(arow + t * 16, achk);
            ldsm4(bAh + off, aH[t]);
            ldsm4(bAl + off, aL[t]);
        }
#pragma unroll
        for (int p = 0; p < 2; p++) {
            const uint32_t off = tile_off(brow_base + p * 16, bchk);
            ldsm4(bBh + off, &bH[p * 4]);
            ldsm4(bBl + off, &bL[p * 4]);
        }
        // TERM-MAJOR: 16 independent MMAs per term -> no accumulator RAW stall
#pragma unroll
        for (int t = 0; t < 4; t++)
#pragma unroll
            for (int u = 0; u < 4; u++)
                mma_bf16(acc[t][u], aH[t], &bH[(u >> 1) * 4 + (u & 1) * 2]);
#pragma unroll
        for (int t = 0; t < 4; t++)
#pragma unroll
            for (int u = 0; u < 4; u++)
                mma_bf16(acc[t][u], aH[t], &bL[(u >> 1) * 4 + (u & 1) * 2]);
#pragma unroll
        for (int t = 0; t < 4; t++)
#pragma unroll
            for (int u = 0; u < 4; u++)
                mma_bf16(acc[t][u], aL[t], &bH[(u >> 1) * 4 + (u & 1) * 2]);
        __syncthreads();
    }

    // ---- epilogue ----------------------------------------------------------
    const int mwarp = m0 + wm * 64;
    const int nwarp = n0 + wn * 32;
    const int g = lane >> 2, q = lane & 3;
#pragma unroll
    for (int u = 0; u < 4; u++) {
        const int n = nwarp + u * 8 + 2 * q;
        const float2 bv = *(const float2*)(bias + n);
#pragma unroll
        for (int t = 0; t < 4; t++) {
            const int m = mwarp + t * 16 + g;
            float2 v0 = make_float2(acc[t][u][0] + bv.x, acc[t][u][1] + bv.y);
            float2 v1 = make_float2(acc[t][u][2] + bv.x, acc[t][u][3] + bv.y);
            if (MODE == 1) {
                *(float2*)(C + (size_t)m * Nfull + n)       = v0;
                *(float2*)(C + (size_t)(m + 8) * Nfull + n) = v1;
            } else {
                const int which = n >> 10;
                const int e = n & 1023;
                const int h = e >> 6;
                const int d = e & 63;
                if (which == 0) { v0.x *= ATTN_SCALE; v0.y *= ATTN_SCALE;
                                  v1.x *= ATTN_SCALE; v1.y *= ATTN_SCALE; }
                __nv_bfloat16* dh = (which == 0) ? g_Qh : (which == 1) ? g_Kh : g_Vh;
                __nv_bfloat16* dl = (which == 0) ? g_Ql : (which == 1) ? g_Kl : g_Vl;
                const int b  = m >> 11;
                const size_t base = (((size_t)(b * NHEADS + h)) * NSEQ) * HDIM + d;
                const size_t o0 = base + (size_t)(m & 2047) * HDIM;
                const size_t o1 = base + (size_t)((m + 8) & 2047) * HDIM;
                *(uint32_t*)(dh + o0) = hipack(v0.x, v0.y);
                *(uint32_t*)(dl + o0) = lopack(v0.x, v0.y);
                *(uint32_t*)(dh + o1) = hipack(v1.x, v1.y);
                *(uint32_t*)(dl + o1) = lopack(v1.x, v1.y);
            }
        }
    }
}

// ---------------------------------------------------------------------------
// Flash attention v3.1: pure bf16, cp.async 2-stage KV, Q smem-resident,
// TERM-MAJOR MMA ordering in both S and PV loops.
// ---------------------------------------------------------------------------
#define FLASH_SMEM (32768 + 2*32768)   // Q(hi+lo 32KB) + 2 KV stages (32KB each)

__global__ __launch_bounds__(256, 2) void flash_mma_v3()
{
    extern __shared__ __align__(16) uint8_t sb[];
    const uint32_t uQh = smem_u32(sb);
    const uint32_t uQl = uQh + 16384;

    const int tid  = threadIdx.x;
    const int lane = tid & 31;
    const int wid  = tid >> 5;
    const int mt   = blockIdx.x;       // q tile (0..15)
    const int bh   = blockIdx.y;       // 0..31

    const size_t kvbase = (size_t)bh * NSEQ * HDIM;
    const __nv_bfloat16* Qhg = g_Qh + kvbase + (size_t)mt * 128 * HDIM;
    const __nv_bfloat16* Qlg = g_Ql + kvbase + (size_t)mt * 128 * HDIM;

    // Q load: 128 rows x 8 chunks x (hi,lo)
    {
        const int r = tid >> 1;                 // 0..127
        const int cb = (tid & 1) * 4;           // chunk base 0 or 4
#pragma unroll
        for (int c = 0; c < 4; c++) {
            cp16(uQh + swz128(r, cb + c), Qhg + (size_t)r * HDIM + (cb + c) * 8);
            cp16(uQl + swz128(r, cb + c), Qlg + (size_t)r * HDIM + (cb + c) * 8);
        }
    }

    auto issue_kv = [&](int t, int buf) {
        const uint32_t base = uQh + 32768 + buf * 32768;
        const __nv_bfloat16* Ks_h = g_Kh + kvbase + (size_t)t * 64 * HDIM;
        const __nv_bfloat16* Ks_l = g_Kl + kvbase + (size_t)t * 64 * HDIM;
        const __nv_bfloat16* Vs_h = g_Vh + kvbase + (size_t)t * 64 * HDIM;
        const __nv_bfloat16* Vs_l = g_Vl + kvbase + (size_t)t * 64 * HDIM;
#pragma unroll
        for (int i = 0; i < 2; i++) {
            const int id = tid + i * 256;       // 0..511
            const int r = id >> 3, c = id & 7;
            const uint32_t off = swz128(r, c);
            const size_t src = (size_t)r * HDIM + c * 8;
            cp16(base + off,          Ks_h + src);
            cp16(base + 8192 + off,   Ks_l + src);
            cp16(base + 16384 + off,  Vs_h + src);
            cp16(base + 24576 + off,  Vs_l + src);
        }
    };

    issue_kv(0, 0);
    CP_COMMIT();

    float of[8][4];
#pragma unroll
    for (int u = 0; u < 8; u++)
#pragma unroll
        for (int e = 0; e < 4; e++) of[u][e] = 0.f;
    float m0 = -1e30f, m1 = -1e30f, l0 = 0.f, l1 = 0.f;

    const int qrow = wid * 16 + (lane & 15);
    const int qsel = lane >> 4;
    const int brow = (lane & 7) + ((lane >> 4) << 3);
    const int bsel = (lane >> 3) & 1;
    const int vrow_l = lane & 15;
    const int vsel   = lane >> 4;

    for (int t = 0; t < NSEQ / 64; t++) {
        CP_WAIT0();
        __syncthreads();
        if (t + 1 < NSEQ / 64) { issue_kv(t + 1, (t + 1) & 1); CP_COMMIT(); }

        const uint32_t kvb = uQh + 32768 + (t & 1) * 32768;
        const uint32_t uKh = kvb, uKl = kvb + 8192;
        const uint32_t uVh = kvb + 16384, uVl = kvb + 24576;

        // ---- S = Q @ K^T (3-term, term-major) -----------------------------
        float sf[8][4];
#pragma unroll
        for (int u = 0; u < 8; u++)
#pragma unroll
            for (int e = 0; e < 4; e++) sf[u][e] = 0.f;

#pragma unroll
        for (int kc = 0; kc < 4; kc++) {
            uint32_t qh[4], ql[4];
            ldsm4(uQh + swz128(qrow, 2 * kc + qsel), qh);
            ldsm4(uQl + swz128(qrow, 2 * kc + qsel), ql);
            uint32_t bb[16];
#pragma unroll
            for (int nb = 0; nb < 4; nb++)
                ldsm4(uKh + swz128(nb * 16 + brow, 2 * kc + bsel), &bb[nb * 4]);
            // term 1: qh * Kh  (8 independent accs)
#pragma unroll
            for (int u = 0; u < 8; u++)
                mma_bf16(sf[u], qh, &bb[(u >> 1) * 4 + (u & 1) * 2]);
            // term 2: ql * Kh
#pragma unroll
            for (int u = 0; u < 8; u++)
                mma_bf16(sf[u], ql, &bb[(u >> 1) * 4 + (u & 1) * 2]);
            // term 3: qh * Kl
#pragma unroll
            for (int nb = 0; nb < 4; nb++)
                ldsm4(uKl + swz128(nb * 16 + brow, 2 * kc + bsel), &bb[nb * 4]);
#pragma unroll
            for (int u = 0; u < 8; u++)
                mma_bf16(sf[u], qh, &bb[(u >> 1) * 4 + (u & 1) * 2]);
        }

        // ---- online softmax ----------------------------------------------
        {
            float mx0 = -1e30f, mx1 = -1e30f;
#pragma unroll
            for (int u = 0; u < 8; u++) {
                mx0 = fmaxf(mx0, fmaxf(sf[u][0], sf[u][1]));
                mx1 = fmaxf(mx1, fmaxf(sf[u][2], sf[u][3]));
            }
            mx0 = fmaxf(mx0, __shfl_xor_sync(0xffffffffu, mx0, 1));
            mx0 = fmaxf(mx0, __shfl_xor_sync(0xffffffffu, mx0, 2));
            mx1 = fmaxf(mx1, __shfl_xor_sync(0xffffffffu, mx1, 1));
            mx1 = fmaxf(mx1, __shfl_xor_sync(0xffffffffu, mx1, 2));

            float mn0 = fmaxf(m0, mx0), mn1 = fmaxf(m1, mx1);
            float c0 = __expf(m0 - mn0), c1 = __expf(m1 - mn1);
            m0 = mn0; m1 = mn1;
            float s0 = 0.f, s1 = 0.f;
#pragma unroll
            for (int u = 0; u < 8; u++) {
                float p0 = __expf(sf[u][0] - mn0);
                float p1 = __expf(sf[u][1] - mn0);
                float p2 = __expf(sf[u][2] - mn1);
                float p3 = __expf(sf[u][3] - mn1);
                s0 += p0 + p1; s1 += p2 + p3;
                sf[u][0] = p0; sf[u][1] = p1; sf[u][2] = p2; sf[u][3] = p3;
            }
            s0 += __shfl_xor_sync(0xffffffffu, s0, 1);
            s0 += __shfl_xor_sync(0xffffffffu, s0, 2);
            s1 += __shfl_xor_sync(0xffffffffu, s1, 1);
            s1 += __shfl_xor_sync(0xffffffffu, s1, 2);
            l0 = l0 * c0 + s0; l1 = l1 * c1 + s1;
#pragma unroll
            for (int u = 0; u < 8; u++) {
                of[u][0] *= c0; of[u][1] *= c0;
                of[u][2] *= c1; of[u][3] *= c1;
            }
        }

        // ---- P frags (register hi/lo) -------------------------------------
        uint32_t pH[4][4], pL[4][4];
#pragma unroll
        for (int kc = 0; kc < 4; kc++) {
            pH[kc][0] = hipack(sf[2*kc][0],   sf[2*kc][1]);
            pH[kc][1] = hipack(sf[2*kc][2],   sf[2*kc][3]);
            pH[kc][2] = hipack(sf[2*kc+1][0], sf[2*kc+1][1]);
            pH[kc][3] = hipack(sf[2*kc+1][2], sf[2*kc+1][3]);
            pL[kc][0] = lopack(sf[2*kc][0],   sf[2*kc][1]);
            pL[kc][1] = lopack(sf[2*kc][2],   sf[2*kc][3]);
            pL[kc][2] = lopack(sf[2*kc+1][0], sf[2*kc+1][1]);
            pL[kc][3] = lopack(sf[2*kc+1][2], sf[2*kc+1][3]);
        }

        // ---- O += P @ V (3-term, term-major; V via ldmatrix.trans) --------
#pragma unroll
        for (int kc = 0; kc < 4; kc++) {
            uint32_t vv[16];
            const int row = 16 * kc + vrow_l;
#pragma unroll
            for (int vp = 0; vp < 4; vp++)
                ldsm4t(uVh + swz128(row, 2 * vp + vsel), &vv[vp * 4]);
            // term 1: pH * Vh
#pragma unroll
            for (int u = 0; u < 8; u++)
                mma_bf16(of[u], pH[kc], &vv[(u >> 1) * 4 + (u & 1) * 2]);
            // term 2: pL * Vh
#pragma unroll
            for (int u = 0; u < 8; u++)
                mma_bf16(of[u], pL[kc], &vv[(u >> 1) * 4 + (u & 1) * 2]);
            // term 3: pH * Vl
#pragma unroll
            for (int vp = 0; vp < 4; vp++)
                ldsm4t(uVl + swz128(row, 2 * vp + vsel), &vv[vp * 4]);
#pragma unroll
            for (int u = 0; u < 8; u++)
                mma_bf16(of[u], pH[kc], &vv[(u >> 1) * 4 + (u & 1) * 2]);
        }
    }

    // ---- epilogue: normalize, write AO as bf16 hi/lo [B*N, E] --------------
    const float inv0 = __fdividef(1.f, l0);
    const float inv1 = __fdividef(1.f, l1);
    const int b = bh >> 4, h = bh & 15;
    const int g = lane >> 2, q = lane & 3;
    const int nrow = mt * 128 + wid * 16 + g;
    const size_t r0 = ((size_t)(b * NSEQ + nrow)) * EMBED + h * HDIM;
    const size_t r1 = r0 + (size_t)8 * EMBED;
#pragma unroll
    for (int u = 0; u < 8; u++) {
        const int col = 8 * u + 2 * q;
        float x0 = of[u][0] * inv0, y0 = of[u][1] * inv0;
        float x1 = of[u][2] * inv1, y1 = of[u][3] * inv1;
        *(uint32_t*)(g_AOh + r0 + col) = hipack(x0, y0);
        *(uint32_t*)(g_AOl + r0 + col) = lopack(x0, y0);
        *(uint32_t*)(g_AOh + r1 + col) = hipack(x1, y1);
        *(uint32_t*)(g_AOl + r1 + col) = lopack(x1, y1);
    }
}

// ---------------------------------------------------------------------------
extern "C" void kernel_launch(void* const* d_in, const int* in_sizes, int n_in,
                              void* d_out, int out_size)
{
    const float* x     = (const float*)d_in[0];
    const float* W_qkv = (const float*)d_in[1];
    const float* b_qkv = (const float*)d_in[2];
    const float* W_out = (const float*)d_in[3];
    const float* b_out = (const float*)d_in[4];
    float* out = (float*)d_out;

    __nv_bfloat16 *xh, *xl, *wqh, *wql, *woh, *wol, *aoh, *aol;
    cudaGetSymbolAddress((void**)&xh,  g_Xh);
    cudaGetSymbolAddress((void**)&xl,  g_Xl);
    cudaGetSymbolAddress((void**)&wqh, g_Wqh);
    cudaGetSymbolAddress((void**)&wql, g_Wql);
    cudaGetSymbolAddress((void**)&woh, g_Woh);
    cudaGetSymbolAddress((void**)&wol, g_Wol);
    cudaGetSymbolAddress((void**)&aoh, g_AOh);
    cudaGetSymbolAddress((void**)&aol, g_AOl);

    cudaFuncSetAttribute(flash_mma_v3,
                         cudaFuncAttributeMaxDynamicSharedMemorySize, FLASH_SMEM);

    // 0) one-time conversions
    convert_hl_kernel<<<(MTOT * EMBED / 4) / 256, 256>>>(x, xh, xl);
    transpose_hl_kernel<<<dim3(3*EMBED/32, EMBED/32), dim3(32, 8)>>>(W_qkv, wqh, wql, EMBED, 3*EMBED);
    transpose_hl_kernel<<<dim3(EMBED/32,   EMBED/32), dim3(32, 8)>>>(W_out, woh, wol, EMBED, EMBED);

    // 1) QKV projection -> Q(scaled)/K/V bf16 hi/lo head-major
    gemm_bf16_kernel<0><<<dim3(3*EMBED/128, MTOT/128), 256>>>(
        xh, xl, wqh, wql, b_qkv, nullptr, 3*EMBED);

    // 2) flash attention -> AO bf16 hi/lo
    flash_mma_v3<<<dim3(NSEQ/128, NB*NHEADS), 256, FLASH_SMEM>>>();

    // 3) output projection -> d_out (fp32)
    gemm_bf16_kernel<1><<<dim3(EMBED/128, MTOT/128), 256>>>(
        aoh, aol, woh, wol, b_out, out, EMBED);
}